// round 1
// baseline (speedup 1.0000x reference)
#include <cuda_runtime.h>

#define NN   8192
#define FIN  512
#define FO   256
#define ALPHA 0.2f
#define MASKF 9e-15f

// Scratch (device globals — no allocation allowed)
__device__ __align__(16) float g_h [NN * FO];
__device__ __align__(16) float g_f1[NN];
__device__ __align__(16) float g_f2[NN];

// ---------------------------------------------------------------------------
// Kernel A: h = x @ W   (8192x512 @ 512x256), 64x64 tile, 4x4 micro
// ---------------------------------------------------------------------------
__global__ void k_h(const float* __restrict__ x, const float* __restrict__ W) {
    __shared__ float sx[64 * 17];   // padded
    __shared__ float sw[16 * 64];
    int t  = threadIdx.x;
    int tx = t & 15, ty = t >> 4;
    int i0 = blockIdx.y * 64;
    int j0 = blockIdx.x * 64;
    float acc[4][4] = {};

    for (int k0 = 0; k0 < FIN; k0 += 16) {
        #pragma unroll
        for (int l = 0; l < 4; ++l) {
            int idx = t + (l << 8);           // 0..1023
            int r = idx >> 4, kk = idx & 15;
            sx[r * 17 + kk] = x[(i0 + r) * FIN + k0 + kk];
        }
        #pragma unroll
        for (int l = 0; l < 4; ++l) {
            int idx = t + (l << 8);
            int kk = idx >> 6, c = idx & 63;
            sw[kk * 64 + c] = W[(k0 + kk) * FO + j0 + c];
        }
        __syncthreads();
        #pragma unroll
        for (int kk = 0; kk < 16; ++kk) {
            float av[4], bv[4];
            #pragma unroll
            for (int u = 0; u < 4; ++u) av[u] = sx[(ty * 4 + u) * 17 + kk];
            #pragma unroll
            for (int v = 0; v < 4; ++v) bv[v] = sw[kk * 64 + tx * 4 + v];
            #pragma unroll
            for (int u = 0; u < 4; ++u)
                #pragma unroll
                for (int v = 0; v < 4; ++v)
                    acc[u][v] += av[u] * bv[v];
        }
        __syncthreads();
    }
    #pragma unroll
    for (int u = 0; u < 4; ++u)
        #pragma unroll
        for (int v = 0; v < 4; ++v)
            g_h[(i0 + ty * 4 + u) * FO + j0 + tx * 4 + v] = acc[u][v];
}

// ---------------------------------------------------------------------------
// Kernel B: f1 = h @ a1, f2 = h @ a2   (one warp per row)
// ---------------------------------------------------------------------------
__global__ void k_f(const float* __restrict__ a) {
    int t = threadIdx.x;
    int warp = t >> 5, lane = t & 31;
    int row = blockIdx.x * 8 + warp;
    float s1 = 0.f, s2 = 0.f;
    #pragma unroll
    for (int l = 0; l < 8; ++l) {
        int k = lane + (l << 5);
        float hv = g_h[row * FO + k];
        s1 += hv * a[k];
        s2 += hv * a[FO + k];
    }
    #pragma unroll
    for (int off = 16; off; off >>= 1) {
        s1 += __shfl_xor_sync(0xffffffffu, s1, off);
        s2 += __shfl_xor_sync(0xffffffffu, s2, off);
    }
    if (lane == 0) { g_f1[row] = s1; g_f2[row] = s2; }
}

// ---------------------------------------------------------------------------
// Packed f32x2 helpers (FFMA2 — only reachable via PTX)
// ---------------------------------------------------------------------------
__device__ __forceinline__ unsigned long long pk2(float lo, float hi) {
    unsigned long long r;
    asm("mov.b64 %0, {%1, %2};" : "=l"(r) : "f"(lo), "f"(hi));
    return r;
}
__device__ __forceinline__ void fma2(unsigned long long& d,
                                     unsigned long long a,
                                     unsigned long long b) {
    asm("fma.rn.f32x2 %0, %1, %2, %0;" : "+l"(d) : "l"(a), "l"(b));
}
__device__ __forceinline__ void upk2(unsigned long long v, float& lo, float& hi) {
    asm("mov.b64 {%0, %1}, %2;" : "=f"(lo), "=f"(hi) : "l"(v));
}

// ---------------------------------------------------------------------------
// Kernel C: fused masked-softmax attention + att @ h
//   Per block: 64 rows, all 256 features. Stream j in 64-tiles.
//   Unnormalized accumulation: acc = sum_j exp(s_ij) h_j ; den = sum_j exp(s_ij)
//   (scores bounded; masked entries exp(9e-15) == 1.0f, matching reference)
// ---------------------------------------------------------------------------
#define SMEM_C ((64 * 256 + 64 * 64 + NN + 64 + 64) * 4)

extern __shared__ float smem_c[];

__global__ void __launch_bounds__(256, 1)
k_attn(const int* __restrict__ adj, float* __restrict__ out) {
    float* h_s   = smem_c;              // 64*256
    float* w_s   = h_s + 64 * 256;      // 64*64  [r][j]
    float* f2_a  = w_s + 64 * 64;       // 8192 (full f2)
    float* f1_s  = f2_a + NN;           // 64
    float* den_s = f1_s + 64;           // 64

    int t  = threadIdx.x;
    int tr = t >> 5, tc = t & 31;       // warp id, lane
    int i0 = blockIdx.x * 64;

    // Preload full f2, f1 tile, zero denom
    float4*       f2_a4 = (float4*)f2_a;
    const float4* gf2_4 = (const float4*)g_f2;
    #pragma unroll
    for (int l = 0; l < 8; ++l) f2_a4[t + (l << 8)] = gf2_4[t + (l << 8)];
    if (t < 64) { f1_s[t] = g_f1[i0 + t]; den_s[t] = 0.f; }

    unsigned long long acc[8][4];
    #pragma unroll
    for (int u = 0; u < 8; ++u)
        #pragma unroll
        for (int v = 0; v < 4; ++v) acc[u][v] = 0ULL;

    float dpart[16];
    #pragma unroll
    for (int u = 0; u < 16; ++u) dpart[u] = 0.f;

    float4*       h_s4 = (float4*)h_s;
    const float4* gh4  = (const float4*)g_h;

    __syncthreads();   // f2_a / f1_s ready

    for (int jt = 0; jt < NN / 64; ++jt) {
        int j0 = jt << 6;

        // Load h tile (rows j0..j0+63 are contiguous: plain 64KB copy)
        #pragma unroll
        for (int l = 0; l < 16; ++l)
            h_s4[t + (l << 8)] = gh4[(j0 << 6) + t + (l << 8)];

        // Compute exp-weights tile; adj fully coalesced, w_s writes conflict-free
        #pragma unroll
        for (int it = 0; it < 16; ++it) {
            int idx = t + (it << 8);
            int r = idx >> 6, j = idx & 63;
            int av = adj[(i0 + r) * NN + j0 + j];
            float e  = f1_s[r] + f2_a[j0 + j];
            float lr = e > 0.f ? e : ALPHA * e;
            float s  = (av > 0) ? lr : MASKF;
            float w  = __expf(s);
            w_s[(r << 6) + j] = w;
            dpart[it] += w;            // row (t>>6) + 4*it, fixed per thread
        }
        __syncthreads();

        // GEMM: acc[8 rows][8 feats] += w * h, packed f32x2 FMAs
        #pragma unroll 4
        for (int j = 0; j < 64; ++j) {
            float4 b0 = h_s4[(j << 6) + (tc << 1)];
            float4 b1 = h_s4[(j << 6) + (tc << 1) + 1];
            unsigned long long bp0 = pk2(b0.x, b0.y);
            unsigned long long bp1 = pk2(b0.z, b0.w);
            unsigned long long bp2 = pk2(b1.x, b1.y);
            unsigned long long bp3 = pk2(b1.z, b1.w);
            #pragma unroll
            for (int u = 0; u < 8; ++u) {
                float av = w_s[(((tr << 3) + u) << 6) + j];  // warp-broadcast
                unsigned long long ap = pk2(av, av);
                fma2(acc[u][0], ap, bp0);
                fma2(acc[u][1], ap, bp1);
                fma2(acc[u][2], ap, bp2);
                fma2(acc[u][3], ap, bp3);
            }
        }
        __syncthreads();
    }

    // Reduce per-row denominators
    #pragma unroll
    for (int it = 0; it < 16; ++it)
        atomicAdd(&den_s[(t >> 6) + (it << 2)], dpart[it]);
    __syncthreads();

    // Normalize + write out
    #pragma unroll
    for (int u = 0; u < 8; ++u) {
        int r = (tr << 3) + u;
        float inv = 1.f / den_s[r];
        float o[8];
        upk2(acc[u][0], o[0], o[1]);
        upk2(acc[u][1], o[2], o[3]);
        upk2(acc[u][2], o[4], o[5]);
        upk2(acc[u][3], o[6], o[7]);
        float4* op = (float4*)&out[(i0 + r) * FO + (tc << 3)];
        op[0] = make_float4(o[0] * inv, o[1] * inv, o[2] * inv, o[3] * inv);
        op[1] = make_float4(o[4] * inv, o[5] * inv, o[6] * inv, o[7] * inv);
    }
}

// ---------------------------------------------------------------------------
extern "C" void kernel_launch(void* const* d_in, const int* in_sizes, int n_in,
                              void* d_out, int out_size) {
    const float* x   = (const float*)d_in[0];
    const int*   adj = (const int*)  d_in[1];
    const float* W   = (const float*)d_in[2];
    const float* a   = (const float*)d_in[3];
    float*       out = (float*)d_out;

    cudaFuncSetAttribute(k_attn, cudaFuncAttributeMaxDynamicSharedMemorySize, SMEM_C);

    k_h   <<<dim3(4, 128), 256>>>(x, W);
    k_f   <<<1024, 256>>>(a);
    k_attn<<<128, 256, SMEM_C>>>(adj, out);
}

// round 3
// speedup vs baseline: 2.8687x; 2.8687x over previous
#include <cuda_runtime.h>
#include <cuda_bf16.h>
#include <cstdint>

#define NN   8192
#define FIN  512
#define FO   256
#define ALPHA 0.2f
#define MASKF 9e-15f

#define KT     32
#define MROWS  128
#define KHALF  4096
#define TILES  128
#define THREADS 512

// Scratch (device globals — no allocation allowed)
__device__ __align__(16) float    g_h    [NN * FO];
__device__ __align__(16) uint32_t g_hb_hi[NN * FO / 2];   // bf16x2 [i][f]
__device__ __align__(16) uint32_t g_hb_lo[NN * FO / 2];
__device__ __align__(16) float    g_pn   [2 * NN * FO];
__device__ __align__(16) float    g_pd   [2 * NN];
__device__ __align__(16) float    g_f1   [NN];
__device__ __align__(16) float    g_f2   [NN];

// ---------------------------------------------------------------------------
// helpers
// ---------------------------------------------------------------------------
__device__ __forceinline__ uint32_t smem_u32(const void* p) {
    uint32_t a;
    asm("{ .reg .u64 t; cvta.to.shared.u64 t, %1; cvt.u32.u64 %0, t; }"
        : "=r"(a) : "l"(p));
    return a;
}
// pack two floats to bf16x2: low halfword = lo (first in memory), high = hi
__device__ __forceinline__ uint32_t bfx2(float lo, float hi) {
    uint32_t r;
    asm("cvt.rn.bf16x2.f32 %0, %1, %2;" : "=r"(r) : "f"(hi), "f"(lo));
    return r;
}
__device__ __forceinline__ float bf_lo_f(uint32_t p) { return __uint_as_float(p << 16); }
__device__ __forceinline__ float bf_hi_f(uint32_t p) { return __uint_as_float(p & 0xFFFF0000u); }

#define CPA16(dst, src) \
    asm volatile("cp.async.cg.shared.global [%0], [%1], 16;" :: "r"(dst), "l"(src) : "memory")
#define CPA_COMMIT() asm volatile("cp.async.commit_group;" ::: "memory")
#define CPA_WAIT0()  asm volatile("cp.async.wait_group 0;" ::: "memory")

#define LDSM4(R0,R1,R2,R3,addr) \
    asm volatile("ldmatrix.sync.aligned.m8n8.x4.shared.b16 {%0,%1,%2,%3}, [%4];" \
        : "=r"(R0), "=r"(R1), "=r"(R2), "=r"(R3) : "r"(addr))
#define LDSM4T(R0,R1,R2,R3,addr) \
    asm volatile("ldmatrix.sync.aligned.m8n8.x4.trans.shared.b16 {%0,%1,%2,%3}, [%4];" \
        : "=r"(R0), "=r"(R1), "=r"(R2), "=r"(R3) : "r"(addr))

#define MMA(D, a0,a1,a2,a3, b0,b1) \
    asm volatile("mma.sync.aligned.m16n8k16.row.col.f32.bf16.bf16.f32 " \
        "{%0,%1,%2,%3}, {%4,%5,%6,%7}, {%8,%9}, {%0,%1,%2,%3};" \
        : "+f"((D)[0]), "+f"((D)[1]), "+f"((D)[2]), "+f"((D)[3]) \
        : "r"(a0), "r"(a1), "r"(a2), "r"(a3), "r"(b0), "r"(b1))

// swizzle for 64B-row tiles (A): XOR byte bits[5:4] with row bits[2:1]
__device__ __forceinline__ uint32_t swzA(uint32_t off) {
    return off ^ ((off >> 3) & 0x30);
}

// ---------------------------------------------------------------------------
// Kernel A: h = x @ W ; emit h bf16 hi/lo in natural [i][f] layout
// ---------------------------------------------------------------------------
__global__ void k_h(const float* __restrict__ x, const float* __restrict__ W) {
    __shared__ float sx[64 * 17];
    __shared__ float sw[16 * 64];
    int t  = threadIdx.x;
    int tx = t & 15, ty = t >> 4;
    int i0 = blockIdx.y * 64;
    int j0 = blockIdx.x * 64;
    float acc[4][4] = {};

    for (int k0 = 0; k0 < FIN; k0 += 16) {
        #pragma unroll
        for (int l = 0; l < 4; ++l) {
            int idx = t + (l << 8);
            int r = idx >> 4, kk = idx & 15;
            sx[r * 17 + kk] = x[(i0 + r) * FIN + k0 + kk];
        }
        #pragma unroll
        for (int l = 0; l < 4; ++l) {
            int idx = t + (l << 8);
            int kk = idx >> 6, c = idx & 63;
            sw[kk * 64 + c] = W[(k0 + kk) * FO + j0 + c];
        }
        __syncthreads();
        #pragma unroll
        for (int kk = 0; kk < 16; ++kk) {
            float av[4], bv[4];
            #pragma unroll
            for (int u = 0; u < 4; ++u) av[u] = sx[(ty * 4 + u) * 17 + kk];
            #pragma unroll
            for (int v = 0; v < 4; ++v) bv[v] = sw[kk * 64 + tx * 4 + v];
            #pragma unroll
            for (int u = 0; u < 4; ++u)
                #pragma unroll
                for (int v = 0; v < 4; ++v)
                    acc[u][v] += av[u] * bv[v];
        }
        __syncthreads();
    }
    #pragma unroll
    for (int u = 0; u < 4; ++u) {
        int row = i0 + ty * 4 + u;
        int col = j0 + tx * 4;
        #pragma unroll
        for (int v = 0; v < 4; ++v)
            g_h[row * FO + col + v] = acc[u][v];
        // bf16 hi/lo split, packed pairs
        uint32_t p0 = bfx2(acc[u][0], acc[u][1]);
        uint32_t p1 = bfx2(acc[u][2], acc[u][3]);
        float l0 = acc[u][0] - bf_lo_f(p0);
        float l1 = acc[u][1] - bf_hi_f(p0);
        float l2 = acc[u][2] - bf_lo_f(p1);
        float l3 = acc[u][3] - bf_hi_f(p1);
        uint32_t q0 = bfx2(l0, l1);
        uint32_t q1 = bfx2(l2, l3);
        int pi = (row * FO + col) >> 1;
        *(uint2*)&g_hb_hi[pi] = make_uint2(p0, p1);
        *(uint2*)&g_hb_lo[pi] = make_uint2(q0, q1);
    }
}

// ---------------------------------------------------------------------------
// Kernel B: f1 = h @ a1, f2 = h @ a2
// ---------------------------------------------------------------------------
__global__ void k_f(const float* __restrict__ a) {
    int t = threadIdx.x;
    int warp = t >> 5, lane = t & 31;
    int row = blockIdx.x * 8 + warp;
    float s1 = 0.f, s2 = 0.f;
    #pragma unroll
    for (int l = 0; l < 8; ++l) {
        int k = lane + (l << 5);
        float hv = g_h[row * FO + k];
        s1 += hv * a[k];
        s2 += hv * a[FO + k];
    }
    #pragma unroll
    for (int off = 16; off; off >>= 1) {
        s1 += __shfl_xor_sync(0xffffffffu, s1, off);
        s2 += __shfl_xor_sync(0xffffffffu, s2, off);
    }
    if (lane == 0) { g_f1[row] = s1; g_f2[row] = s2; }
}

// ---------------------------------------------------------------------------
// Kernel C: fused attention on mma.sync bf16 (3-term split), K-split 2
//  CTA: 128 rows x 4096 j. 16 warps (2M x 8N), warp tile 64x32.
//  Stage (64KB x2): A_hi 8K | A_lo 8K | B_hi 16K | B_lo 16K | adj 16K
// ---------------------------------------------------------------------------
#define STG_SZ  65536
#define SMEM_C  (1024 + 2 * STG_SZ)
#define OFF_AH  0
#define OFF_AL  8192
#define OFF_BH  16384
#define OFF_BL  32768
#define OFF_ADJ 49152

__device__ __forceinline__ void issue_stage(uint32_t stg, const int* __restrict__ adj,
                                            int i0, int jb, int t) {
    // adj: 128 rows x 32 ints; 1024 chunks of 16B
    #pragma unroll
    for (int l = 0; l < 2; ++l) {
        int id = t * 2 + l;
        int r = id >> 3, c = id & 7;
        uint32_t dst = stg + OFF_ADJ + r * 128 + ((c * 16) ^ ((r & 7) << 4));
        const void* src = adj + (size_t)(i0 + r) * NN + jb + c * 4;
        CPA16(dst, src);
    }
    // B: h bf16 [j][f], 32 rows x 512B per array; 1024 chunks each
    #pragma unroll
    for (int l = 0; l < 2; ++l) {
        int id = t * 2 + l;
        int j = id >> 5, c = id & 31;
        uint32_t off = (j << 9) + ((c * 16) ^ ((j & 7) << 4));
        const char* sh = (const char*)g_hb_hi + ((size_t)(jb + j) * FO + c * 8) * 2;
        const char* sl = (const char*)g_hb_lo + ((size_t)(jb + j) * FO + c * 8) * 2;
        CPA16(stg + OFF_BH + off, sh);
        CPA16(stg + OFF_BL + off, sl);
    }
}

__global__ void __launch_bounds__(THREADS, 1)
k_attn(const int* __restrict__ adj) {
    extern __shared__ char sm[];
    uint32_t sb = smem_u32(sm);
    float* f1_s  = (float*)sm;            // 128 floats
    float* den_s = (float*)(sm + 512);    // 128 floats

    int t    = threadIdx.x;
    int bx   = blockIdx.x;
    int i0   = (bx >> 1) * MROWS;
    int half = bx & 1;
    int jb0  = half * KHALF;

    if (t < MROWS) { f1_s[t] = g_f1[i0 + t]; den_s[t] = 0.f; }

    float d[4][4][4];
    #pragma unroll
    for (int a = 0; a < 4; ++a)
        #pragma unroll
        for (int b = 0; b < 4; ++b)
            #pragma unroll
            for (int c = 0; c < 4; ++c) d[a][b][c] = 0.f;
    float dpart = 0.f;

    int lane = t & 31, wid = t >> 5;
    int wm = wid & 1, wn = wid >> 1;
    int wr = t >> 2, wq = t & 3;          // w-compute: row, j-quad

    // prefetch stage 0
    issue_stage(sb + 1024, adj, i0, jb0, t);
    CPA_COMMIT();

    for (int tl = 0; tl < TILES; ++tl) {
        int s = tl & 1;
        uint32_t stgb = sb + 1024 + s * STG_SZ;
        char*    stgp = sm + 1024 + s * STG_SZ;
        int jb = jb0 + tl * KT;

        CPA_WAIT0();
        __syncthreads();                 // stage tl visible; prev mma done

        if (tl + 1 < TILES) {
            issue_stage(sb + 1024 + (s ^ 1) * STG_SZ, adj, i0, jb + KT, t);
            CPA_COMMIT();
        }

        // ---- compute w tile (128x32) -> A_hi / A_lo (bf16, swizzled) ----
        {
            uint32_t ao1 = OFF_ADJ + wr * 128 + (((wq * 2) * 16) ^ ((wr & 7) << 4));
            uint32_t ao2 = OFF_ADJ + wr * 128 + (((wq * 2 + 1) * 16) ^ ((wr & 7) << 4));
            int4 a0 = *(const int4*)(stgp + ao1);
            int4 a1 = *(const int4*)(stgp + ao2);
            int jq = jb + wq * 8;
            float4 f2a = *(const float4*)(g_f2 + jq);
            float4 f2b = *(const float4*)(g_f2 + jq + 4);
            float f1v = f1_s[wr];
            float w[8];
            int   av[8] = {a0.x, a0.y, a0.z, a0.w, a1.x, a1.y, a1.z, a1.w};
            float fv[8] = {f2a.x, f2a.y, f2a.z, f2a.w, f2b.x, f2b.y, f2b.z, f2b.w};
            #pragma unroll
            for (int e = 0; e < 8; ++e) {
                float sc = f1v + fv[e];
                float lr = sc > 0.f ? sc : ALPHA * sc;
                float sv = (av[e] > 0) ? lr : MASKF;
                w[e] = __expf(sv);
                dpart += w[e];
            }
            uint32_t hi[4], lo[4];
            #pragma unroll
            for (int p = 0; p < 4; ++p) {
                hi[p] = bfx2(w[2*p], w[2*p+1]);
                float l0 = w[2*p]   - bf_lo_f(hi[p]);
                float l1 = w[2*p+1] - bf_hi_f(hi[p]);
                lo[p] = bfx2(l0, l1);
            }
            uint32_t aoff = swzA((uint32_t)(wr * 64 + wq * 16));
            *(uint4*)(stgp + OFF_AH + aoff) = make_uint4(hi[0], hi[1], hi[2], hi[3]);
            *(uint4*)(stgp + OFF_AL + aoff) = make_uint4(lo[0], lo[1], lo[2], lo[3]);
        }
        __syncthreads();

        // ---- mma: 2 k16 steps, 3 passes each ----
        #pragma unroll
        for (int k0 = 0; k0 < KT; k0 += 16) {
            uint32_t ah[4][4], bh[8], bl[8];
            int arow = wm * 64 + (lane & 15);
            int acol = (k0 + ((lane >> 4) << 3)) * 2;
            // B frags (trans): j rows, f cols
            int bj = k0 + (lane & 7) + ((lane & 8) ? 8 : 0);
            #pragma unroll
            for (int hB = 0; hB < 2; ++hB) {
                int f = wn * 32 + hB * 16 + ((lane & 16) ? 8 : 0);
                uint32_t off = ((uint32_t)bj << 9) + (((uint32_t)f * 2) ^ ((bj & 7) << 4));
                LDSM4T(bh[hB*4+0], bh[hB*4+1], bh[hB*4+2], bh[hB*4+3], stgb + OFF_BH + off);
                LDSM4T(bl[hB*4+0], bl[hB*4+1], bl[hB*4+2], bl[hB*4+3], stgb + OFF_BL + off);
            }
            // A hi frags
            #pragma unroll
            for (int mt = 0; mt < 4; ++mt) {
                uint32_t off = swzA((uint32_t)((arow + mt * 16) * 64 + acol));
                LDSM4(ah[mt][0], ah[mt][1], ah[mt][2], ah[mt][3], stgb + OFF_AH + off);
            }
            // pass 1: w_hi * h_hi ; pass 2: w_hi * h_lo
            #pragma unroll
            for (int mt = 0; mt < 4; ++mt)
                #pragma unroll
                for (int nt = 0; nt < 4; ++nt) {
                    MMA(d[mt][nt], ah[mt][0], ah[mt][1], ah[mt][2], ah[mt][3],
                        bh[nt*2], bh[nt*2+1]);
                    MMA(d[mt][nt], ah[mt][0], ah[mt][1], ah[mt][2], ah[mt][3],
                        bl[nt*2], bl[nt*2+1]);
                }
            // pass 3: w_lo * h_hi (reuse A regs)
            #pragma unroll
            for (int mt = 0; mt < 4; ++mt) {
                uint32_t off = swzA((uint32_t)((arow + mt * 16) * 64 + acol));
                LDSM4(ah[mt][0], ah[mt][1], ah[mt][2], ah[mt][3], stgb + OFF_AL + off);
            }
            #pragma unroll
            for (int mt = 0; mt < 4; ++mt)
                #pragma unroll
                for (int nt = 0; nt < 4; ++nt)
                    MMA(d[mt][nt], ah[mt][0], ah[mt][1], ah[mt][2], ah[mt][3],
                        bh[nt*2], bh[nt*2+1]);
        }
    }

    // denominators
    atomicAdd(&den_s[wr], dpart);
    __syncthreads();
    if (t < MROWS) g_pd[(size_t)half * NN + i0 + t] = den_s[t];

    // numerator partials
    float* base = g_pn + (size_t)half * NN * FO;
    #pragma unroll
    for (int mt = 0; mt < 4; ++mt) {
        int m = wm * 64 + mt * 16 + (lane >> 2);
        #pragma unroll
        for (int nt = 0; nt < 4; ++nt) {
            int col = wn * 32 + nt * 8 + (lane & 3) * 2;
            float* dst = base + (size_t)(i0 + m) * FO + col;
            *(float2*)dst            = make_float2(d[mt][nt][0], d[mt][nt][1]);
            *(float2*)(dst + 8 * FO) = make_float2(d[mt][nt][2], d[mt][nt][3]);
        }
    }
}

// ---------------------------------------------------------------------------
// Kernel D: combine K-split halves + normalize
// ---------------------------------------------------------------------------
__global__ void k_norm(float* __restrict__ out) {
    int idx = blockIdx.x * 256 + threadIdx.x;
    const float4* p0 = (const float4*)g_pn;
    const float4* p1 = (const float4*)(g_pn + (size_t)NN * FO);
    float4 a = p0[idx], b = p1[idx];
    int row = idx >> 6;
    float inv = 1.f / (g_pd[row] + g_pd[NN + row]);
    float4 o;
    o.x = (a.x + b.x) * inv;
    o.y = (a.y + b.y) * inv;
    o.z = (a.z + b.z) * inv;
    o.w = (a.w + b.w) * inv;
    ((float4*)out)[idx] = o;
}

// ---------------------------------------------------------------------------
extern "C" void kernel_launch(void* const* d_in, const int* in_sizes, int n_in,
                              void* d_out, int out_size) {
    const float* x   = (const float*)d_in[0];
    const int*   adj = (const int*)  d_in[1];
    const float* W   = (const float*)d_in[2];
    const float* a   = (const float*)d_in[3];
    float*       out = (float*)d_out;

    cudaFuncSetAttribute(k_attn, cudaFuncAttributeMaxDynamicSharedMemorySize, SMEM_C);

    k_h   <<<dim3(4, 128), 256>>>(x, W);
    k_f   <<<1024, 256>>>(a);
    k_attn<<<128, THREADS, SMEM_C>>>(adj);
    k_norm<<<2048, 256>>>(out);
}

// round 4
// speedup vs baseline: 3.4980x; 1.2194x over previous
#include <cuda_runtime.h>
#include <cuda_bf16.h>
#include <cstdint>

#define NN   8192
#define FIN  512
#define FO   256
#define ALPHA 0.2f
#define MASKF 9e-15f

#define KT     64
#define MROWS  128
#define KHALF  4096
#define TILES  (KHALF/KT)    // 64
#define THREADS 512

#define XPAIRS (NN*FIN/2)
#define WPAIRS (FIN*FO/2)

// Scratch (device globals — no allocation allowed)
__device__ __align__(16) uint32_t g_xb_hi[XPAIRS];
__device__ __align__(16) uint32_t g_xb_lo[XPAIRS];
__device__ __align__(16) uint32_t g_wb_hi[WPAIRS];
__device__ __align__(16) uint32_t g_wb_lo[WPAIRS];
__device__ __align__(16) uint32_t g_hb_hi[NN * FO / 2];   // bf16x2 [i][f]
__device__ __align__(16) uint32_t g_hb_lo[NN * FO / 2];
__device__ __align__(16) float    g_pn   [2 * NN * FO];
__device__ __align__(16) float    g_pd   [2 * NN];
__device__ __align__(16) float    g_f1   [NN];
__device__ __align__(16) float    g_f2   [NN];

// ---------------------------------------------------------------------------
// helpers
// ---------------------------------------------------------------------------
__device__ __forceinline__ uint32_t smem_u32(const void* p) {
    uint32_t a;
    asm("{ .reg .u64 t; cvta.to.shared.u64 t, %1; cvt.u32.u64 %0, t; }"
        : "=r"(a) : "l"(p));
    return a;
}
__device__ __forceinline__ uint32_t bfx2(float lo, float hi) {
    uint32_t r;
    asm("cvt.rn.bf16x2.f32 %0, %1, %2;" : "=r"(r) : "f"(hi), "f"(lo));
    return r;
}
__device__ __forceinline__ float bf_lo_f(uint32_t p) { return __uint_as_float(p << 16); }
__device__ __forceinline__ float bf_hi_f(uint32_t p) { return __uint_as_float(p & 0xFFFF0000u); }

#define CPA16(dst, src) \
    asm volatile("cp.async.cg.shared.global [%0], [%1], 16;" :: "r"(dst), "l"(src) : "memory")
#define CPA_COMMIT() asm volatile("cp.async.commit_group;" ::: "memory")
#define CPA_WAIT0()  asm volatile("cp.async.wait_group 0;" ::: "memory")

#define LDSM4(R0,R1,R2,R3,addr) \
    asm volatile("ldmatrix.sync.aligned.m8n8.x4.shared.b16 {%0,%1,%2,%3}, [%4];" \
        : "=r"(R0), "=r"(R1), "=r"(R2), "=r"(R3) : "r"(addr))
#define LDSM4T(R0,R1,R2,R3,addr) \
    asm volatile("ldmatrix.sync.aligned.m8n8.x4.trans.shared.b16 {%0,%1,%2,%3}, [%4];" \
        : "=r"(R0), "=r"(R1), "=r"(R2), "=r"(R3) : "r"(addr))

#define MMA(D, a0,a1,a2,a3, b0,b1) \
    asm volatile("mma.sync.aligned.m16n8k16.row.col.f32.bf16.bf16.f32 " \
        "{%0,%1,%2,%3}, {%4,%5,%6,%7}, {%8,%9}, {%0,%1,%2,%3};" \
        : "+f"((D)[0]), "+f"((D)[1]), "+f"((D)[2]), "+f"((D)[3]) \
        : "r"(a0), "r"(a1), "r"(a2), "r"(a3), "r"(b0), "r"(b1))

// ---------------------------------------------------------------------------
// k_conv: fp32 -> bf16 hi/lo split of x and W; zero g_pd
// ---------------------------------------------------------------------------
__global__ void k_conv(const float* __restrict__ x, const float* __restrict__ W) {
    int idx = blockIdx.x * 256 + threadIdx.x;
    if (idx < 2 * NN) g_pd[idx] = 0.f;
    if (idx < XPAIRS) {
        float2 v = ((const float2*)x)[idx];
        uint32_t h = bfx2(v.x, v.y);
        g_xb_hi[idx] = h;
        g_xb_lo[idx] = bfx2(v.x - bf_lo_f(h), v.y - bf_hi_f(h));
    } else if (idx < XPAIRS + WPAIRS) {
        int j = idx - XPAIRS;
        float2 v = ((const float2*)W)[j];
        uint32_t h = bfx2(v.x, v.y);
        g_wb_hi[j] = h;
        g_wb_lo[j] = bfx2(v.x - bf_lo_f(h), v.y - bf_hi_f(h));
    }
}

// ---------------------------------------------------------------------------
// k_h_mma: h = x @ W on mma.sync bf16 3-term; epilogue emits g_hb hi/lo and
//          f1/f2 (h@a1, h@a2) via quad-reduce. CTA = 64 rows x 256 cols.
//          8 warps (1M x 8N), warp tile 64x32. K chunks of 64 (8 chunks).
//  Stage (80KB x2): A_hi 8K | A_lo 8K | B_hi 32K | B_lo 32K
// ---------------------------------------------------------------------------
#define HSTG     81920
#define H_AH     0
#define H_AL     8192
#define H_BH     16384
#define H_BL     49152
#define SMEM_H   (2 * HSTG)

__device__ __forceinline__ void issue_h(uint32_t stg, int i0, int k0, int t) {
    #pragma unroll
    for (int l = 0; l < 2; ++l) {           // A: 512 chunks per array
        int id = t + l * 256;
        int row = id >> 3, c = id & 7;
        uint32_t dst = stg + H_AH + row * 128 + ((c * 16) ^ ((row & 7) << 4));
        const char* sh = (const char*)g_xb_hi + ((size_t)(i0 + row) * FIN + k0 + c * 8) * 2;
        const char* sl = (const char*)g_xb_lo + ((size_t)(i0 + row) * FIN + k0 + c * 8) * 2;
        CPA16(dst, sh);
        CPA16(dst + (H_AL - H_AH), sl);
    }
    #pragma unroll
    for (int l = 0; l < 8; ++l) {           // B: 2048 chunks per array
        int id = t + l * 256;
        int kk = id >> 5, c = id & 31;
        uint32_t dst = stg + H_BH + (kk << 9) + ((c * 16) ^ ((kk & 7) << 4));
        const char* sh = (const char*)g_wb_hi + ((size_t)(k0 + kk) * FO + c * 8) * 2;
        const char* sl = (const char*)g_wb_lo + ((size_t)(k0 + kk) * FO + c * 8) * 2;
        CPA16(dst, sh);
        CPA16(dst + (H_BL - H_BH), sl);
    }
}

__global__ void __launch_bounds__(256, 1)
k_h_mma(const float* __restrict__ a) {
    extern __shared__ char sm[];
    __shared__ float a_s[2 * FO];
    __shared__ float s1_s[64], s2_s[64];
    uint32_t sb = smem_u32(sm);
    int t = threadIdx.x, lane = t & 31, wid = t >> 5;
    int i0 = blockIdx.x * 64;

    a_s[t] = a[t];
    a_s[t + 256] = a[t + 256];
    if (t < 64) { s1_s[t] = 0.f; s2_s[t] = 0.f; }

    float d[4][4][4];
    #pragma unroll
    for (int m = 0; m < 4; ++m)
        #pragma unroll
        for (int n = 0; n < 4; ++n)
            #pragma unroll
            for (int c = 0; c < 4; ++c) d[m][n][c] = 0.f;

    issue_h(sb, i0, 0, t);
    CPA_COMMIT();

    for (int kc = 0; kc < 8; ++kc) {
        int s = kc & 1;
        uint32_t stgb = sb + s * HSTG;
        CPA_WAIT0();
        __syncthreads();
        if (kc + 1 < 8) { issue_h(sb + (s ^ 1) * HSTG, i0, (kc + 1) * 64, t); CPA_COMMIT(); }

        #pragma unroll
        for (int k0 = 0; k0 < 64; k0 += 16) {
            uint32_t ah[4][4], bh[8], bl[8];
            int arow = lane & 15;
            int acol = (k0 + ((lane >> 4) << 3)) * 2;
            int bj = k0 + (lane & 7) + ((lane & 8) ? 8 : 0);
            #pragma unroll
            for (int hB = 0; hB < 2; ++hB) {
                int f = wid * 32 + hB * 16 + ((lane & 16) ? 8 : 0);
                uint32_t off = ((uint32_t)bj << 9) + (((uint32_t)f * 2) ^ ((bj & 7) << 4));
                LDSM4T(bh[hB*4+0], bh[hB*4+1], bh[hB*4+2], bh[hB*4+3], stgb + H_BH + off);
                LDSM4T(bl[hB*4+0], bl[hB*4+1], bl[hB*4+2], bl[hB*4+3], stgb + H_BL + off);
            }
            #pragma unroll
            for (int mt = 0; mt < 4; ++mt) {
                uint32_t off = (uint32_t)((arow + mt * 16) * 128 + acol) ^ (uint32_t)((arow & 7) << 4);
                LDSM4(ah[mt][0], ah[mt][1], ah[mt][2], ah[mt][3], stgb + H_AH + off);
            }
            #pragma unroll
            for (int mt = 0; mt < 4; ++mt)
                #pragma unroll
                for (int nt = 0; nt < 4; ++nt) {
                    MMA(d[mt][nt], ah[mt][0], ah[mt][1], ah[mt][2], ah[mt][3],
                        bh[nt*2], bh[nt*2+1]);
                    MMA(d[mt][nt], ah[mt][0], ah[mt][1], ah[mt][2], ah[mt][3],
                        bl[nt*2], bl[nt*2+1]);
                }
            #pragma unroll
            for (int mt = 0; mt < 4; ++mt) {
                uint32_t off = (uint32_t)((arow + mt * 16) * 128 + acol) ^ (uint32_t)((arow & 7) << 4);
                LDSM4(ah[mt][0], ah[mt][1], ah[mt][2], ah[mt][3], stgb + H_AL + off);
            }
            #pragma unroll
            for (int mt = 0; mt < 4; ++mt)
                #pragma unroll
                for (int nt = 0; nt < 4; ++nt)
                    MMA(d[mt][nt], ah[mt][0], ah[mt][1], ah[mt][2], ah[mt][3],
                        bh[nt*2], bh[nt*2+1]);
        }
    }

    // epilogue: store h bf16 hi/lo, accumulate f1/f2 partials
    #pragma unroll
    for (int mt = 0; mt < 4; ++mt) {
        int mloc = mt * 16 + (lane >> 2);
        int mg   = i0 + mloc;
        float r1a = 0.f, r2a = 0.f, r1b = 0.f, r2b = 0.f;
        #pragma unroll
        for (int nt = 0; nt < 4; ++nt) {
            int col = wid * 32 + nt * 8 + (lane & 3) * 2;
            float d0 = d[mt][nt][0], d1 = d[mt][nt][1];
            float d2 = d[mt][nt][2], d3 = d[mt][nt][3];
            uint32_t ph = bfx2(d0, d1);
            g_hb_hi[((size_t)mg * FO + col) >> 1] = ph;
            g_hb_lo[((size_t)mg * FO + col) >> 1] = bfx2(d0 - bf_lo_f(ph), d1 - bf_hi_f(ph));
            uint32_t qh = bfx2(d2, d3);
            g_hb_hi[((size_t)(mg + 8) * FO + col) >> 1] = qh;
            g_hb_lo[((size_t)(mg + 8) * FO + col) >> 1] = bfx2(d2 - bf_lo_f(qh), d3 - bf_hi_f(qh));
            r1a += d0 * a_s[col] + d1 * a_s[col + 1];
            r2a += d0 * a_s[FO + col] + d1 * a_s[FO + col + 1];
            r1b += d2 * a_s[col] + d3 * a_s[col + 1];
            r2b += d2 * a_s[FO + col] + d3 * a_s[FO + col + 1];
        }
        r1a += __shfl_xor_sync(0xffffffffu, r1a, 1); r1a += __shfl_xor_sync(0xffffffffu, r1a, 2);
        r2a += __shfl_xor_sync(0xffffffffu, r2a, 1); r2a += __shfl_xor_sync(0xffffffffu, r2a, 2);
        r1b += __shfl_xor_sync(0xffffffffu, r1b, 1); r1b += __shfl_xor_sync(0xffffffffu, r1b, 2);
        r2b += __shfl_xor_sync(0xffffffffu, r2b, 1); r2b += __shfl_xor_sync(0xffffffffu, r2b, 2);
        if ((lane & 3) == 0) {
            atomicAdd(&s1_s[mloc], r1a);
            atomicAdd(&s2_s[mloc], r2a);
            atomicAdd(&s1_s[mloc + 8], r1b);
            atomicAdd(&s2_s[mloc + 8], r2b);
        }
    }
    __syncthreads();
    if (t < 64) { g_f1[i0 + t] = s1_s[t]; g_f2[i0 + t] = s2_s[t]; }
}

// ---------------------------------------------------------------------------
// k_attn: fused attention, KT=64, single-buffered adj (272B padded rows),
//         double-buffered A/B stages. 16 warps (2M x 8N), warp tile 64x32.
//  Stage (96KB x2): A_hi 16K | A_lo 16K | B_hi 32K | B_lo 32K; adj 34K
// ---------------------------------------------------------------------------
#define STG     98304
#define A_AH    0
#define A_AL    16384
#define A_BH    32768
#define A_BL    65536
#define ADJOFF  (2 * STG)                 // 196608
#define SMEM_C  (ADJOFF + 128 * 272)      // 231424 <= 232448

__device__ __forceinline__ void issue_attn(uint32_t sb, int s, const int* __restrict__ adj,
                                           int i0, int jb, int t) {
    uint32_t stg = sb + s * STG;
    #pragma unroll
    for (int l = 0; l < 4; ++l) {          // B: 2048 chunks per array
        int id = t + l * 512;
        int j = id >> 5, c = id & 31;
        uint32_t dst = stg + A_BH + (j << 9) + ((c * 16) ^ ((j & 7) << 4));
        const char* sh = (const char*)g_hb_hi + ((size_t)(jb + j) * FO + c * 8) * 2;
        const char* sl = (const char*)g_hb_lo + ((size_t)(jb + j) * FO + c * 8) * 2;
        CPA16(dst, sh);
        CPA16(dst + (A_BL - A_BH), sl);
    }
    #pragma unroll
    for (int l = 0; l < 4; ++l) {          // adj: 2048 chunks, padded rows
        int id = t + l * 512;
        int r = id >> 4, c = id & 15;
        uint32_t dst = sb + ADJOFF + r * 272 + c * 16;
        const void* src = adj + (size_t)(i0 + r) * NN + jb + c * 4;
        CPA16(dst, src);
    }
}

__global__ void __launch_bounds__(THREADS, 1)
k_attn(const int* __restrict__ adj) {
    extern __shared__ char sm[];
    uint32_t sb = smem_u32(sm);

    int t    = threadIdx.x;
    int lane = t & 31, wid = t >> 5;
    int wm   = wid & 1, wn = wid >> 1;
    int bx   = blockIdx.x;
    int i0   = (bx >> 1) * MROWS;
    int half = bx & 1;
    int jb0  = half * KHALF;

    int   wr  = t & 127, wq = t >> 7;      // w-compute: row, j-16-group
    float f1r = g_f1[i0 + wr];

    float d[4][4][4];
    #pragma unroll
    for (int m = 0; m < 4; ++m)
        #pragma unroll
        for (int n = 0; n < 4; ++n)
            #pragma unroll
            for (int c = 0; c < 4; ++c) d[m][n][c] = 0.f;
    float dpart = 0.f;

    issue_attn(sb, 0, adj, i0, jb0, t);
    CPA_COMMIT();

    for (int tl = 0; tl < TILES; ++tl) {
        int s = tl & 1;
        uint32_t stgb = sb + s * STG;
        char*    stgp = sm + s * STG;
        int jb = jb0 + tl * KT;

        CPA_WAIT0();
        __syncthreads();

        // ---- w-compute: 16 elements/thread -> A_hi / A_lo bf16 swizzled ----
        {
            const char* adjp = sm + ADJOFF + wr * 272 + wq * 64;
            int4 a0 = *(const int4*)(adjp);
            int4 a1 = *(const int4*)(adjp + 16);
            int4 a2 = *(const int4*)(adjp + 32);
            int4 a3 = *(const int4*)(adjp + 48);
            int jq = jb + wq * 16;
            float4 f20 = *(const float4*)(g_f2 + jq);
            float4 f21 = *(const float4*)(g_f2 + jq + 4);
            float4 f22 = *(const float4*)(g_f2 + jq + 8);
            float4 f23 = *(const float4*)(g_f2 + jq + 12);
            int   av[16] = {a0.x,a0.y,a0.z,a0.w, a1.x,a1.y,a1.z,a1.w,
                            a2.x,a2.y,a2.z,a2.w, a3.x,a3.y,a3.z,a3.w};
            float fv[16] = {f20.x,f20.y,f20.z,f20.w, f21.x,f21.y,f21.z,f21.w,
                            f22.x,f22.y,f22.z,f22.w, f23.x,f23.y,f23.z,f23.w};
            float w[16];
            #pragma unroll
            for (int e = 0; e < 16; ++e) {
                float sc = f1r + fv[e];
                float lr = sc > 0.f ? sc : ALPHA * sc;
                float sv = (av[e] > 0) ? lr : MASKF;
                w[e] = __expf(sv);
                dpart += w[e];
            }
            uint32_t hi[8], lo[8];
            #pragma unroll
            for (int p = 0; p < 8; ++p) {
                hi[p] = bfx2(w[2*p], w[2*p+1]);
                lo[p] = bfx2(w[2*p] - bf_lo_f(hi[p]), w[2*p+1] - bf_hi_f(hi[p]));
            }
            uint32_t base = (uint32_t)(wr * 128 + wq * 32);
            uint32_t xo   = (uint32_t)((wr & 7) << 4);
            uint32_t o0 = base ^ xo, o1 = (base + 16) ^ xo;
            *(uint4*)(stgp + A_AH + o0) = make_uint4(hi[0], hi[1], hi[2], hi[3]);
            *(uint4*)(stgp + A_AH + o1) = make_uint4(hi[4], hi[5], hi[6], hi[7]);
            *(uint4*)(stgp + A_AL + o0) = make_uint4(lo[0], lo[1], lo[2], lo[3]);
            *(uint4*)(stgp + A_AL + o1) = make_uint4(lo[4], lo[5], lo[6], lo[7]);
        }
        __syncthreads();

        if (tl + 1 < TILES) {
            issue_attn(sb, s ^ 1, adj, i0, jb + KT, t);
            CPA_COMMIT();
        }

        // ---- mma: 4 k16 steps, 3 passes each ----
        #pragma unroll
        for (int k0 = 0; k0 < KT; k0 += 16) {
            uint32_t ah[4][4], bh[8], bl[8];
            int arow = wm * 64 + (lane & 15);
            int acol = (k0 + ((lane >> 4) << 3)) * 2;
            int bj = k0 + (lane & 7) + ((lane & 8) ? 8 : 0);
            #pragma unroll
            for (int hB = 0; hB < 2; ++hB) {
                int f = wn * 32 + hB * 16 + ((lane & 16) ? 8 : 0);
                uint32_t off = ((uint32_t)bj << 9) + (((uint32_t)f * 2) ^ ((bj & 7) << 4));
                LDSM4T(bh[hB*4+0], bh[hB*4+1], bh[hB*4+2], bh[hB*4+3], stgb + A_BH + off);
                LDSM4T(bl[hB*4+0], bl[hB*4+1], bl[hB*4+2], bl[hB*4+3], stgb + A_BL + off);
            }
            #pragma unroll
            for (int mt = 0; mt < 4; ++mt) {
                uint32_t off = (uint32_t)((arow + mt * 16) * 128 + acol) ^ (uint32_t)((arow & 7) << 4);
                LDSM4(ah[mt][0], ah[mt][1], ah[mt][2], ah[mt][3], stgb + A_AH + off);
            }
            #pragma unroll
            for (int mt = 0; mt < 4; ++mt)
                #pragma unroll
                for (int nt = 0; nt < 4; ++nt) {
                    MMA(d[mt][nt], ah[mt][0], ah[mt][1], ah[mt][2], ah[mt][3],
                        bh[nt*2], bh[nt*2+1]);
                    MMA(d[mt][nt], ah[mt][0], ah[mt][1], ah[mt][2], ah[mt][3],
                        bl[nt*2], bl[nt*2+1]);
                }
            #pragma unroll
            for (int mt = 0; mt < 4; ++mt) {
                uint32_t off = (uint32_t)((arow + mt * 16) * 128 + acol) ^ (uint32_t)((arow & 7) << 4);
                LDSM4(ah[mt][0], ah[mt][1], ah[mt][2], ah[mt][3], stgb + A_AL + off);
            }
            #pragma unroll
            for (int mt = 0; mt < 4; ++mt)
                #pragma unroll
                for (int nt = 0; nt < 4; ++nt)
                    MMA(d[mt][nt], ah[mt][0], ah[mt][1], ah[mt][2], ah[mt][3],
                        bh[nt*2], bh[nt*2+1]);
        }
    }

    // denominators (g_pd zeroed by k_conv)
    atomicAdd(&g_pd[(size_t)half * NN + i0 + wr], dpart);

    // numerator partials
    float* base = g_pn + (size_t)half * NN * FO;
    #pragma unroll
    for (int mt = 0; mt < 4; ++mt) {
        int m = wm * 64 + mt * 16 + (lane >> 2);
        #pragma unroll
        for (int nt = 0; nt < 4; ++nt) {
            int col = wn * 32 + nt * 8 + (lane & 3) * 2;
            float* dst = base + (size_t)(i0 + m) * FO + col;
            *(float2*)dst            = make_float2(d[mt][nt][0], d[mt][nt][1]);
            *(float2*)(dst + 8 * FO) = make_float2(d[mt][nt][2], d[mt][nt][3]);
        }
    }
}

// ---------------------------------------------------------------------------
// k_norm: combine K-split halves + normalize
// ---------------------------------------------------------------------------
__global__ void k_norm(float* __restrict__ out) {
    int idx = blockIdx.x * 256 + threadIdx.x;
    const float4* p0 = (const float4*)g_pn;
    const float4* p1 = (const float4*)(g_pn + (size_t)NN * FO);
    float4 a = p0[idx], b = p1[idx];
    int row = idx >> 6;
    float inv = 1.f / (g_pd[row] + g_pd[NN + row]);
    float4 o;
    o.x = (a.x + b.x) * inv;
    o.y = (a.y + b.y) * inv;
    o.z = (a.z + b.z) * inv;
    o.w = (a.w + b.w) * inv;
    ((float4*)out)[idx] = o;
}

// ---------------------------------------------------------------------------
extern "C" void kernel_launch(void* const* d_in, const int* in_sizes, int n_in,
                              void* d_out, int out_size) {
    const float* x   = (const float*)d_in[0];
    const int*   adj = (const int*)  d_in[1];
    const float* W   = (const float*)d_in[2];
    const float* a   = (const float*)d_in[3];
    float*       out = (float*)d_out;

    cudaFuncSetAttribute(k_h_mma, cudaFuncAttributeMaxDynamicSharedMemorySize, SMEM_H);
    cudaFuncSetAttribute(k_attn,  cudaFuncAttributeMaxDynamicSharedMemorySize, SMEM_C);

    k_conv <<<(XPAIRS + WPAIRS) / 256, 256>>>(x, W);
    k_h_mma<<<128, 256, SMEM_H>>>(a);
    k_attn <<<128, THREADS, SMEM_C>>>(adj);
    k_norm <<<2048, 256>>>(out);
}

// round 5
// speedup vs baseline: 4.4208x; 1.2638x over previous
#include <cuda_runtime.h>
#include <cuda_bf16.h>
#include <cuda_fp16.h>
#include <cstdint>

#define NN   8192
#define FIN  512
#define FO   256
#define ALPHA 0.2f
#define MASKF 9e-15f

#define KT     64
#define MROWS  128
#define KHALF  4096
#define TILES  (KHALF/KT)    // 64
#define THREADS 512

#define XPAIRS (NN*FIN/2)
#define WPAIRS (FIN*FO/2)

// Scratch (device globals — no allocation allowed)
__device__ __align__(16) uint32_t g_xb_hi[XPAIRS];
__device__ __align__(16) uint32_t g_xb_lo[XPAIRS];
__device__ __align__(16) uint32_t g_wb_hi[WPAIRS];
__device__ __align__(16) uint32_t g_wb_lo[WPAIRS];
__device__ __align__(16) uint32_t g_hb_hi[NN * FO / 2];   // fp16x2 [i][f]
__device__ __align__(16) uint32_t g_hb_lo[NN * FO / 2];
__device__ __align__(16) float    g_pn   [2 * NN * FO];
__device__ __align__(16) float    g_pd   [2 * NN];
__device__ __align__(16) float    g_f1   [NN];
__device__ __align__(16) float    g_f2   [NN];
__device__ uint32_t g_m2i;                                 // ordered-int max f2

// ---------------------------------------------------------------------------
// helpers
// ---------------------------------------------------------------------------
__device__ __forceinline__ uint32_t smem_u32(const void* p) {
    uint32_t a;
    asm("{ .reg .u64 t; cvta.to.shared.u64 t, %1; cvt.u32.u64 %0, t; }"
        : "=r"(a) : "l"(p));
    return a;
}
__device__ __forceinline__ uint32_t bfx2(float lo, float hi) {
    uint32_t r;
    asm("cvt.rn.bf16x2.f32 %0, %1, %2;" : "=r"(r) : "f"(hi), "f"(lo));
    return r;
}
__device__ __forceinline__ float bf_lo_f(uint32_t p) { return __uint_as_float(p << 16); }
__device__ __forceinline__ float bf_hi_f(uint32_t p) { return __uint_as_float(p & 0xFFFF0000u); }

__device__ __forceinline__ uint32_t fkey(float f) {
    uint32_t b = __float_as_uint(f);
    return (b & 0x80000000u) ? ~b : (b | 0x80000000u);
}
__device__ __forceinline__ float funkey(uint32_t k) {
    uint32_t b = (k & 0x80000000u) ? (k & 0x7FFFFFFFu) : ~k;
    return __uint_as_float(b);
}

#define CPA16(dst, src) \
    asm volatile("cp.async.cg.shared.global [%0], [%1], 16;" :: "r"(dst), "l"(src) : "memory")
#define CPA_COMMIT() asm volatile("cp.async.commit_group;" ::: "memory")
#define CPA_WAIT0()  asm volatile("cp.async.wait_group 0;" ::: "memory")

#define LDSM4(R0,R1,R2,R3,addr) \
    asm volatile("ldmatrix.sync.aligned.m8n8.x4.shared.b16 {%0,%1,%2,%3}, [%4];" \
        : "=r"(R0), "=r"(R1), "=r"(R2), "=r"(R3) : "r"(addr))
#define LDSM4T(R0,R1,R2,R3,addr) \
    asm volatile("ldmatrix.sync.aligned.m8n8.x4.trans.shared.b16 {%0,%1,%2,%3}, [%4];" \
        : "=r"(R0), "=r"(R1), "=r"(R2), "=r"(R3) : "r"(addr))

#define MMAB(D, a0,a1,a2,a3, b0,b1) \
    asm volatile("mma.sync.aligned.m16n8k16.row.col.f32.bf16.bf16.f32 " \
        "{%0,%1,%2,%3}, {%4,%5,%6,%7}, {%8,%9}, {%0,%1,%2,%3};" \
        : "+f"((D)[0]), "+f"((D)[1]), "+f"((D)[2]), "+f"((D)[3]) \
        : "r"(a0), "r"(a1), "r"(a2), "r"(a3), "r"(b0), "r"(b1))

#define MMAH(D, a0,a1,a2,a3, b0,b1) \
    asm volatile("mma.sync.aligned.m16n8k16.row.col.f32.f16.f16.f32 " \
        "{%0,%1,%2,%3}, {%4,%5,%6,%7}, {%8,%9}, {%0,%1,%2,%3};" \
        : "+f"((D)[0]), "+f"((D)[1]), "+f"((D)[2]), "+f"((D)[3]) \
        : "r"(a0), "r"(a1), "r"(a2), "r"(a3), "r"(b0), "r"(b1))

// ---------------------------------------------------------------------------
// k_conv: fp32 -> bf16 hi/lo split of x and W; zero g_pd; init g_m2i
// ---------------------------------------------------------------------------
__global__ void k_conv(const float* __restrict__ x, const float* __restrict__ W) {
    int idx = blockIdx.x * 256 + threadIdx.x;
    if (idx == 0) g_m2i = 0u;
    if (idx < 2 * NN) g_pd[idx] = 0.f;
    if (idx < XPAIRS) {
        float2 v = ((const float2*)x)[idx];
        uint32_t h = bfx2(v.x, v.y);
        g_xb_hi[idx] = h;
        g_xb_lo[idx] = bfx2(v.x - bf_lo_f(h), v.y - bf_hi_f(h));
    } else if (idx < XPAIRS + WPAIRS) {
        int j = idx - XPAIRS;
        float2 v = ((const float2*)W)[j];
        uint32_t h = bfx2(v.x, v.y);
        g_wb_hi[j] = h;
        g_wb_lo[j] = bfx2(v.x - bf_lo_f(h), v.y - bf_hi_f(h));
    }
}

// ---------------------------------------------------------------------------
// k_h_mma: h = x @ W on mma.sync bf16 3-term; epilogue emits g_hb fp16 hi/lo,
//          f1/f2, and atomic-max of f2 into g_m2i.
// ---------------------------------------------------------------------------
#define HSTG     81920
#define H_AH     0
#define H_AL     8192
#define H_BH     16384
#define H_BL     49152
#define SMEM_H   (2 * HSTG)

__device__ __forceinline__ void issue_h(uint32_t stg, int i0, int k0, int t) {
    #pragma unroll
    for (int l = 0; l < 2; ++l) {
        int id = t + l * 256;
        int row = id >> 3, c = id & 7;
        uint32_t dst = stg + H_AH + row * 128 + ((c * 16) ^ ((row & 7) << 4));
        const char* sh = (const char*)g_xb_hi + ((size_t)(i0 + row) * FIN + k0 + c * 8) * 2;
        const char* sl = (const char*)g_xb_lo + ((size_t)(i0 + row) * FIN + k0 + c * 8) * 2;
        CPA16(dst, sh);
        CPA16(dst + (H_AL - H_AH), sl);
    }
    #pragma unroll
    for (int l = 0; l < 8; ++l) {
        int id = t + l * 256;
        int kk = id >> 5, c = id & 31;
        uint32_t dst = stg + H_BH + (kk << 9) + ((c * 16) ^ ((kk & 7) << 4));
        const char* sh = (const char*)g_wb_hi + ((size_t)(k0 + kk) * FO + c * 8) * 2;
        const char* sl = (const char*)g_wb_lo + ((size_t)(k0 + kk) * FO + c * 8) * 2;
        CPA16(dst, sh);
        CPA16(dst + (H_BL - H_BH), sl);
    }
}

__global__ void __launch_bounds__(256, 1)
k_h_mma(const float* __restrict__ a) {
    extern __shared__ char sm[];
    __shared__ float a_s[2 * FO];
    __shared__ float s1_s[64], s2_s[64];
    uint32_t sb = smem_u32(sm);
    int t = threadIdx.x, lane = t & 31, wid = t >> 5;
    int i0 = blockIdx.x * 64;

    a_s[t] = a[t];
    a_s[t + 256] = a[t + 256];
    if (t < 64) { s1_s[t] = 0.f; s2_s[t] = 0.f; }

    float d[4][4][4];
    #pragma unroll
    for (int m = 0; m < 4; ++m)
        #pragma unroll
        for (int n = 0; n < 4; ++n)
            #pragma unroll
            for (int c = 0; c < 4; ++c) d[m][n][c] = 0.f;

    issue_h(sb, i0, 0, t);
    CPA_COMMIT();

    for (int kc = 0; kc < 8; ++kc) {
        int s = kc & 1;
        uint32_t stgb = sb + s * HSTG;
        CPA_WAIT0();
        __syncthreads();
        if (kc + 1 < 8) { issue_h(sb + (s ^ 1) * HSTG, i0, (kc + 1) * 64, t); CPA_COMMIT(); }

        #pragma unroll
        for (int k0 = 0; k0 < 64; k0 += 16) {
            uint32_t ah[4][4], bh[8], bl[8];
            int arow = lane & 15;
            int acol = (k0 + ((lane >> 4) << 3)) * 2;
            int bj = k0 + (lane & 7) + ((lane & 8) ? 8 : 0);
            #pragma unroll
            for (int hB = 0; hB < 2; ++hB) {
                int f = wid * 32 + hB * 16 + ((lane & 16) ? 8 : 0);
                uint32_t off = ((uint32_t)bj << 9) + (((uint32_t)f * 2) ^ ((bj & 7) << 4));
                LDSM4T(bh[hB*4+0], bh[hB*4+1], bh[hB*4+2], bh[hB*4+3], stgb + H_BH + off);
                LDSM4T(bl[hB*4+0], bl[hB*4+1], bl[hB*4+2], bl[hB*4+3], stgb + H_BL + off);
            }
            #pragma unroll
            for (int mt = 0; mt < 4; ++mt) {
                uint32_t off = (uint32_t)((arow + mt * 16) * 128 + acol) ^ (uint32_t)((arow & 7) << 4);
                LDSM4(ah[mt][0], ah[mt][1], ah[mt][2], ah[mt][3], stgb + H_AH + off);
            }
            #pragma unroll
            for (int mt = 0; mt < 4; ++mt)
                #pragma unroll
                for (int nt = 0; nt < 4; ++nt) {
                    MMAB(d[mt][nt], ah[mt][0], ah[mt][1], ah[mt][2], ah[mt][3],
                         bh[nt*2], bh[nt*2+1]);
                    MMAB(d[mt][nt], ah[mt][0], ah[mt][1], ah[mt][2], ah[mt][3],
                         bl[nt*2], bl[nt*2+1]);
                }
            #pragma unroll
            for (int mt = 0; mt < 4; ++mt) {
                uint32_t off = (uint32_t)((arow + mt * 16) * 128 + acol) ^ (uint32_t)((arow & 7) << 4);
                LDSM4(ah[mt][0], ah[mt][1], ah[mt][2], ah[mt][3], stgb + H_AL + off);
            }
            #pragma unroll
            for (int mt = 0; mt < 4; ++mt)
                #pragma unroll
                for (int nt = 0; nt < 4; ++nt)
                    MMAB(d[mt][nt], ah[mt][0], ah[mt][1], ah[mt][2], ah[mt][3],
                         bh[nt*2], bh[nt*2+1]);
        }
    }

    // epilogue: store h fp16 hi/lo, accumulate f1/f2 partials
    #pragma unroll
    for (int mt = 0; mt < 4; ++mt) {
        int mloc = mt * 16 + (lane >> 2);
        int mg   = i0 + mloc;
        float r1a = 0.f, r2a = 0.f, r1b = 0.f, r2b = 0.f;
        #pragma unroll
        for (int nt = 0; nt < 4; ++nt) {
            int col = wid * 32 + nt * 8 + (lane & 3) * 2;
            float d0 = d[mt][nt][0], d1 = d[mt][nt][1];
            float d2 = d[mt][nt][2], d3 = d[mt][nt][3];
            half2 ph = __floats2half2_rn(d0, d1);
            g_hb_hi[((size_t)mg * FO + col) >> 1] = *(uint32_t*)&ph;
            half2 pl = __floats2half2_rn(d0 - __low2float(ph), d1 - __high2float(ph));
            g_hb_lo[((size_t)mg * FO + col) >> 1] = *(uint32_t*)&pl;
            half2 qh = __floats2half2_rn(d2, d3);
            g_hb_hi[((size_t)(mg + 8) * FO + col) >> 1] = *(uint32_t*)&qh;
            half2 ql = __floats2half2_rn(d2 - __low2float(qh), d3 - __high2float(qh));
            g_hb_lo[((size_t)(mg + 8) * FO + col) >> 1] = *(uint32_t*)&ql;
            r1a += d0 * a_s[col] + d1 * a_s[col + 1];
            r2a += d0 * a_s[FO + col] + d1 * a_s[FO + col + 1];
            r1b += d2 * a_s[col] + d3 * a_s[col + 1];
            r2b += d2 * a_s[FO + col] + d3 * a_s[FO + col + 1];
        }
        r1a += __shfl_xor_sync(0xffffffffu, r1a, 1); r1a += __shfl_xor_sync(0xffffffffu, r1a, 2);
        r2a += __shfl_xor_sync(0xffffffffu, r2a, 1); r2a += __shfl_xor_sync(0xffffffffu, r2a, 2);
        r1b += __shfl_xor_sync(0xffffffffu, r1b, 1); r1b += __shfl_xor_sync(0xffffffffu, r1b, 2);
        r2b += __shfl_xor_sync(0xffffffffu, r2b, 1); r2b += __shfl_xor_sync(0xffffffffu, r2b, 2);
        if ((lane & 3) == 0) {
            atomicAdd(&s1_s[mloc], r1a);
            atomicAdd(&s2_s[mloc], r2a);
            atomicAdd(&s1_s[mloc + 8], r1b);
            atomicAdd(&s2_s[mloc + 8], r2b);
        }
    }
    __syncthreads();
    if (t < 64) { g_f1[i0 + t] = s1_s[t]; g_f2[i0 + t] = s2_s[t]; }
    if (t < 64) {
        float m = s2_s[t];
        #pragma unroll
        for (int off = 16; off; off >>= 1)
            m = fmaxf(m, __shfl_xor_sync(0xffffffffu, m, off));
        if ((t & 31) == 0) atomicMax(&g_m2i, fkey(m));
    }
}

// ---------------------------------------------------------------------------
// k_attn: fused attention, fp16 2-pass with per-row shift b = max(f1+M2, 0).
//  Stage (80KB x2): A(w fp16) 16K | B_hi 32K | B_lo 32K; adj 34K padded.
// ---------------------------------------------------------------------------
#define STG     81920
#define A_AH    0
#define A_BH    16384
#define A_BL    49152
#define ADJOFF  (2 * STG)                 // 163840
#define SMEM_C  (ADJOFF + 128 * 272)      // 198656

__device__ __forceinline__ void issue_attn(uint32_t sb, int s, const int* __restrict__ adj,
                                           int i0, int jb, int t) {
    uint32_t stg = sb + s * STG;
    #pragma unroll
    for (int l = 0; l < 4; ++l) {          // B: 2048 chunks per array
        int id = t + l * 512;
        int j = id >> 5, c = id & 31;
        uint32_t dst = stg + A_BH + (j << 9) + ((c * 16) ^ ((j & 7) << 4));
        const char* sh = (const char*)g_hb_hi + ((size_t)(jb + j) * FO + c * 8) * 2;
        const char* sl = (const char*)g_hb_lo + ((size_t)(jb + j) * FO + c * 8) * 2;
        CPA16(dst, sh);
        CPA16(dst + (A_BL - A_BH), sl);
    }
    #pragma unroll
    for (int l = 0; l < 4; ++l) {          // adj: 2048 chunks, padded rows
        int id = t + l * 512;
        int r = id >> 4, c = id & 15;
        uint32_t dst = sb + ADJOFF + r * 272 + c * 16;
        const void* src = adj + (size_t)(i0 + r) * NN + jb + c * 4;
        CPA16(dst, src);
    }
}

__global__ void __launch_bounds__(THREADS, 1)
k_attn(const int* __restrict__ adj) {
    extern __shared__ char sm[];
    uint32_t sb = smem_u32(sm);

    int t    = threadIdx.x;
    int lane = t & 31, wid = t >> 5;
    int wm   = wid & 1, wn = wid >> 1;
    int bx   = blockIdx.x;
    int i0   = (bx >> 1) * MROWS;
    int half = bx & 1;
    int jb0  = half * KHALF;

    int   wr  = t & 127, wq = t >> 7;      // w-compute: row, j-16-group
    float f1r = g_f1[i0 + wr];
    float m2  = funkey(g_m2i);
    float bsh = fmaxf(f1r + m2, 0.f);      // per-row exponent shift

    float d[4][4][4];
    #pragma unroll
    for (int m = 0; m < 4; ++m)
        #pragma unroll
        for (int n = 0; n < 4; ++n)
            #pragma unroll
            for (int c = 0; c < 4; ++c) d[m][n][c] = 0.f;
    float dpart = 0.f;

    issue_attn(sb, 0, adj, i0, jb0, t);
    CPA_COMMIT();

    for (int tl = 0; tl < TILES; ++tl) {
        int s = tl & 1;
        uint32_t stgb = sb + s * STG;
        char*    stgp = sm + s * STG;
        int jb = jb0 + tl * KT;

        CPA_WAIT0();
        __syncthreads();

        // ---- w-compute: 16 elements/thread -> A (fp16, swizzled) ----
        {
            const char* adjp = sm + ADJOFF + wr * 272 + wq * 64;
            int4 a0 = *(const int4*)(adjp);
            int4 a1 = *(const int4*)(adjp + 16);
            int4 a2 = *(const int4*)(adjp + 32);
            int4 a3 = *(const int4*)(adjp + 48);
            int jq = jb + wq * 16;
            float4 f20 = *(const float4*)(g_f2 + jq);
            float4 f21 = *(const float4*)(g_f2 + jq + 4);
            float4 f22 = *(const float4*)(g_f2 + jq + 8);
            float4 f23 = *(const float4*)(g_f2 + jq + 12);
            int   av[16] = {a0.x,a0.y,a0.z,a0.w, a1.x,a1.y,a1.z,a1.w,
                            a2.x,a2.y,a2.z,a2.w, a3.x,a3.y,a3.z,a3.w};
            float fv[16] = {f20.x,f20.y,f20.z,f20.w, f21.x,f21.y,f21.z,f21.w,
                            f22.x,f22.y,f22.z,f22.w, f23.x,f23.y,f23.z,f23.w};
            float w[16];
            #pragma unroll
            for (int e = 0; e < 16; ++e) {
                float sc = f1r + fv[e];
                float lr = sc > 0.f ? sc : ALPHA * sc;
                float sv = (av[e] > 0) ? lr : MASKF;
                w[e] = __expf(sv - bsh);
            }
            uint32_t hi[8];
            #pragma unroll
            for (int p = 0; p < 8; ++p) {
                half2 hp = __floats2half2_rn(w[2*p], w[2*p+1]);
                hi[p] = *(uint32_t*)&hp;
                dpart += __low2float(hp) + __high2float(hp);
            }
            uint32_t base = (uint32_t)(wr * 128 + wq * 32);
            uint32_t xo   = (uint32_t)((wr & 7) << 4);
            *(uint4*)(stgp + A_AH + (base ^ xo))        = make_uint4(hi[0], hi[1], hi[2], hi[3]);
            *(uint4*)(stgp + A_AH + ((base + 16) ^ xo)) = make_uint4(hi[4], hi[5], hi[6], hi[7]);
        }
        __syncthreads();

        if (tl + 1 < TILES) {
            issue_attn(sb, s ^ 1, adj, i0, jb + KT, t);
            CPA_COMMIT();
        }

        // ---- mma: 4 k16 steps, 2 passes each ----
        #pragma unroll
        for (int k0 = 0; k0 < KT; k0 += 16) {
            uint32_t ah[4][4], bh[8], bl[8];
            int arow = wm * 64 + (lane & 15);
            int acol = (k0 + ((lane >> 4) << 3)) * 2;
            int bj = k0 + (lane & 7) + ((lane & 8) ? 8 : 0);
            #pragma unroll
            for (int hB = 0; hB < 2; ++hB) {
                int f = wn * 32 + hB * 16 + ((lane & 16) ? 8 : 0);
                uint32_t off = ((uint32_t)bj << 9) + (((uint32_t)f * 2) ^ ((bj & 7) << 4));
                LDSM4T(bh[hB*4+0], bh[hB*4+1], bh[hB*4+2], bh[hB*4+3], stgb + A_BH + off);
                LDSM4T(bl[hB*4+0], bl[hB*4+1], bl[hB*4+2], bl[hB*4+3], stgb + A_BL + off);
            }
            #pragma unroll
            for (int mt = 0; mt < 4; ++mt) {
                uint32_t off = (uint32_t)((arow + mt * 16) * 128 + acol) ^ (uint32_t)((arow & 7) << 4);
                LDSM4(ah[mt][0], ah[mt][1], ah[mt][2], ah[mt][3], stgb + A_AH + off);
            }
            #pragma unroll
            for (int mt = 0; mt < 4; ++mt)
                #pragma unroll
                for (int nt = 0; nt < 4; ++nt) {
                    MMAH(d[mt][nt], ah[mt][0], ah[mt][1], ah[mt][2], ah[mt][3],
                         bh[nt*2], bh[nt*2+1]);
                    MMAH(d[mt][nt], ah[mt][0], ah[mt][1], ah[mt][2], ah[mt][3],
                         bl[nt*2], bl[nt*2+1]);
                }
        }
    }

    // denominators (g_pd zeroed by k_conv)
    atomicAdd(&g_pd[(size_t)half * NN + i0 + wr], dpart);

    // numerator partials
    float* base = g_pn + (size_t)half * NN * FO;
    #pragma unroll
    for (int mt = 0; mt < 4; ++mt) {
        int m = wm * 64 + mt * 16 + (lane >> 2);
        #pragma unroll
        for (int nt = 0; nt < 4; ++nt) {
            int col = wn * 32 + nt * 8 + (lane & 3) * 2;
            float* dst = base + (size_t)(i0 + m) * FO + col;
            *(float2*)dst            = make_float2(d[mt][nt][0], d[mt][nt][1]);
            *(float2*)(dst + 8 * FO) = make_float2(d[mt][nt][2], d[mt][nt][3]);
        }
    }
}

// ---------------------------------------------------------------------------
// k_norm: combine K-split halves + normalize (per-row scale cancels)
// ---------------------------------------------------------------------------
__global__ void k_norm(float* __restrict__ out) {
    int idx = blockIdx.x * 256 + threadIdx.x;
    const float4* p0 = (const float4*)g_pn;
    const float4* p1 = (const float4*)(g_pn + (size_t)NN * FO);
    float4 a = p0[idx], b = p1[idx];
    int row = idx >> 6;
    float inv = 1.f / (g_pd[row] + g_pd[NN + row]);
    float4 o;
    o.x = (a.x + b.x) * inv;
    o.y = (a.y + b.y) * inv;
    o.z = (a.z + b.z) * inv;
    o.w = (a.w + b.w) * inv;
    ((float4*)out)[idx] = o;
}

// ---------------------------------------------------------------------------
extern "C" void kernel_launch(void* const* d_in, const int* in_sizes, int n_in,
                              void* d_out, int out_size) {
    const float* x   = (const float*)d_in[0];
    const int*   adj = (const int*)  d_in[1];
    const float* W   = (const float*)d_in[2];
    const float* a   = (const float*)d_in[3];
    float*       out = (float*)d_out;

    cudaFuncSetAttribute(k_h_mma, cudaFuncAttributeMaxDynamicSharedMemorySize, SMEM_H);
    cudaFuncSetAttribute(k_attn,  cudaFuncAttributeMaxDynamicSharedMemorySize, SMEM_C);

    k_conv <<<(XPAIRS + WPAIRS) / 256, 256>>>(x, W);
    k_h_mma<<<128, 256, SMEM_H>>>(a);
    k_attn <<<128, THREADS, SMEM_C>>>(adj);
    k_norm <<<2048, 256>>>(out);
}

// round 6
// speedup vs baseline: 6.0688x; 1.3728x over previous
#include <cuda_runtime.h>
#include <cuda_bf16.h>
#include <cuda_fp16.h>
#include <cstdint>

#define NN   8192
#define FIN  512
#define FO   256
#define ALPHA 0.2f
#define MASKF 9e-15f

#define KT     64
#define MROWS  128
#define KHALF  4096
#define TILES  (KHALF/KT)    // 64
#define THREADS 512

#define XPAIRS (NN*FIN/2)
#define WPAIRS (FIN*FO/2)

// Scratch (device globals — no allocation allowed)
__device__ __align__(16) uint32_t g_xb_hi[XPAIRS];
__device__ __align__(16) uint32_t g_xb_lo[XPAIRS];
__device__ __align__(16) uint32_t g_wb_hi[WPAIRS];
__device__ __align__(16) uint32_t g_wb_lo[WPAIRS];
__device__ __align__(16) uint32_t g_hb_hi[NN * FO / 2];   // fp16x2 [i][f]
__device__ __align__(16) float    g_pn   [2 * NN * FO];
__device__ __align__(16) float    g_pd   [2 * NN];
__device__ __align__(16) float    g_f1   [NN];
__device__ __align__(16) float    g_f2   [NN];
__device__ uint32_t g_m2i;                                 // ordered-int max f2

// ---------------------------------------------------------------------------
// helpers
// ---------------------------------------------------------------------------
__device__ __forceinline__ uint32_t smem_u32(const void* p) {
    uint32_t a;
    asm("{ .reg .u64 t; cvta.to.shared.u64 t, %1; cvt.u32.u64 %0, t; }"
        : "=r"(a) : "l"(p));
    return a;
}
__device__ __forceinline__ uint32_t bfx2(float lo, float hi) {
    uint32_t r;
    asm("cvt.rn.bf16x2.f32 %0, %1, %2;" : "=r"(r) : "f"(hi), "f"(lo));
    return r;
}
__device__ __forceinline__ float bf_lo_f(uint32_t p) { return __uint_as_float(p << 16); }
__device__ __forceinline__ float bf_hi_f(uint32_t p) { return __uint_as_float(p & 0xFFFF0000u); }

__device__ __forceinline__ uint32_t fkey(float f) {
    uint32_t b = __float_as_uint(f);
    return (b & 0x80000000u) ? ~b : (b | 0x80000000u);
}
__device__ __forceinline__ float funkey(uint32_t k) {
    uint32_t b = (k & 0x80000000u) ? (k & 0x7FFFFFFFu) : ~k;
    return __uint_as_float(b);
}

#define CPA16(dst, src) \
    asm volatile("cp.async.cg.shared.global [%0], [%1], 16;" :: "r"(dst), "l"(src) : "memory")
#define CPA_COMMIT() asm volatile("cp.async.commit_group;" ::: "memory")
#define CPA_WAITG(n) asm volatile("cp.async.wait_group %0;" :: "n"(n) : "memory")

#define LDSM4(R0,R1,R2,R3,addr) \
    asm volatile("ldmatrix.sync.aligned.m8n8.x4.shared.b16 {%0,%1,%2,%3}, [%4];" \
        : "=r"(R0), "=r"(R1), "=r"(R2), "=r"(R3) : "r"(addr))
#define LDSM4T(R0,R1,R2,R3,addr) \
    asm volatile("ldmatrix.sync.aligned.m8n8.x4.trans.shared.b16 {%0,%1,%2,%3}, [%4];" \
        : "=r"(R0), "=r"(R1), "=r"(R2), "=r"(R3) : "r"(addr))

#define MMAB(D, a0,a1,a2,a3, b0,b1) \
    asm volatile("mma.sync.aligned.m16n8k16.row.col.f32.bf16.bf16.f32 " \
        "{%0,%1,%2,%3}, {%4,%5,%6,%7}, {%8,%9}, {%0,%1,%2,%3};" \
        : "+f"((D)[0]), "+f"((D)[1]), "+f"((D)[2]), "+f"((D)[3]) \
        : "r"(a0), "r"(a1), "r"(a2), "r"(a3), "r"(b0), "r"(b1))

#define MMAH(D, a0,a1,a2,a3, b0,b1) \
    asm volatile("mma.sync.aligned.m16n8k16.row.col.f32.f16.f16.f32 " \
        "{%0,%1,%2,%3}, {%4,%5,%6,%7}, {%8,%9}, {%0,%1,%2,%3};" \
        : "+f"((D)[0]), "+f"((D)[1]), "+f"((D)[2]), "+f"((D)[3]) \
        : "r"(a0), "r"(a1), "r"(a2), "r"(a3), "r"(b0), "r"(b1))

// ---------------------------------------------------------------------------
// k_conv: fp32 -> bf16 hi/lo split of x and W; zero g_pd; init g_m2i
// ---------------------------------------------------------------------------
__global__ void k_conv(const float* __restrict__ x, const float* __restrict__ W) {
    int idx = blockIdx.x * 256 + threadIdx.x;
    if (idx == 0) g_m2i = 0u;
    if (idx < 2 * NN) g_pd[idx] = 0.f;
    if (idx < XPAIRS) {
        float2 v = ((const float2*)x)[idx];
        uint32_t h = bfx2(v.x, v.y);
        g_xb_hi[idx] = h;
        g_xb_lo[idx] = bfx2(v.x - bf_lo_f(h), v.y - bf_hi_f(h));
    } else if (idx < XPAIRS + WPAIRS) {
        int j = idx - XPAIRS;
        float2 v = ((const float2*)W)[j];
        uint32_t h = bfx2(v.x, v.y);
        g_wb_hi[j] = h;
        g_wb_lo[j] = bfx2(v.x - bf_lo_f(h), v.y - bf_hi_f(h));
    }
}

// ---------------------------------------------------------------------------
// k_h_mma: h = x @ W on mma.sync bf16 3-term; epilogue emits g_hb fp16,
//          f1/f2, and atomic-max of f2 into g_m2i.
// ---------------------------------------------------------------------------
#define HSTG     81920
#define H_AH     0
#define H_AL     8192
#define H_BH     16384
#define H_BL     49152
#define SMEM_H   (2 * HSTG)

__device__ __forceinline__ void issue_h(uint32_t stg, int i0, int k0, int t) {
    #pragma unroll
    for (int l = 0; l < 2; ++l) {
        int id = t + l * 256;
        int row = id >> 3, c = id & 7;
        uint32_t dst = stg + H_AH + row * 128 + ((c * 16) ^ ((row & 7) << 4));
        const char* sh = (const char*)g_xb_hi + ((size_t)(i0 + row) * FIN + k0 + c * 8) * 2;
        const char* sl = (const char*)g_xb_lo + ((size_t)(i0 + row) * FIN + k0 + c * 8) * 2;
        CPA16(dst, sh);
        CPA16(dst + (H_AL - H_AH), sl);
    }
    #pragma unroll
    for (int l = 0; l < 8; ++l) {
        int id = t + l * 256;
        int kk = id >> 5, c = id & 31;
        uint32_t dst = stg + H_BH + (kk << 9) + ((c * 16) ^ ((kk & 7) << 4));
        const char* sh = (const char*)g_wb_hi + ((size_t)(k0 + kk) * FO + c * 8) * 2;
        const char* sl = (const char*)g_wb_lo + ((size_t)(k0 + kk) * FO + c * 8) * 2;
        CPA16(dst, sh);
        CPA16(dst + (H_BL - H_BH), sl);
    }
}

__global__ void __launch_bounds__(256, 1)
k_h_mma(const float* __restrict__ a) {
    extern __shared__ char sm[];
    __shared__ float a_s[2 * FO];
    __shared__ float s1_s[64], s2_s[64];
    uint32_t sb = smem_u32(sm);
    int t = threadIdx.x, lane = t & 31, wid = t >> 5;
    int i0 = blockIdx.x * 64;

    a_s[t] = a[t];
    a_s[t + 256] = a[t + 256];
    if (t < 64) { s1_s[t] = 0.f; s2_s[t] = 0.f; }

    float d[4][4][4];
    #pragma unroll
    for (int m = 0; m < 4; ++m)
        #pragma unroll
        for (int n = 0; n < 4; ++n)
            #pragma unroll
            for (int c = 0; c < 4; ++c) d[m][n][c] = 0.f;

    issue_h(sb, i0, 0, t);
    CPA_COMMIT();

    for (int kc = 0; kc < 8; ++kc) {
        int s = kc & 1;
        uint32_t stgb = sb + s * HSTG;
        CPA_WAITG(0);
        __syncthreads();
        if (kc + 1 < 8) { issue_h(sb + (s ^ 1) * HSTG, i0, (kc + 1) * 64, t); CPA_COMMIT(); }

        #pragma unroll
        for (int k0 = 0; k0 < 64; k0 += 16) {
            uint32_t ah[4][4], bh[8], bl[8];
            int arow = lane & 15;
            int acol = (k0 + ((lane >> 4) << 3)) * 2;
            int bj = k0 + (lane & 7) + ((lane & 8) ? 8 : 0);
            #pragma unroll
            for (int hB = 0; hB < 2; ++hB) {
                int f = wid * 32 + hB * 16 + ((lane & 16) ? 8 : 0);
                uint32_t off = ((uint32_t)bj << 9) + (((uint32_t)f * 2) ^ ((bj & 7) << 4));
                LDSM4T(bh[hB*4+0], bh[hB*4+1], bh[hB*4+2], bh[hB*4+3], stgb + H_BH + off);
                LDSM4T(bl[hB*4+0], bl[hB*4+1], bl[hB*4+2], bl[hB*4+3], stgb + H_BL + off);
            }
            #pragma unroll
            for (int mt = 0; mt < 4; ++mt) {
                uint32_t off = (uint32_t)((arow + mt * 16) * 128 + acol) ^ (uint32_t)((arow & 7) << 4);
                LDSM4(ah[mt][0], ah[mt][1], ah[mt][2], ah[mt][3], stgb + H_AH + off);
            }
            #pragma unroll
            for (int mt = 0; mt < 4; ++mt)
                #pragma unroll
                for (int nt = 0; nt < 4; ++nt) {
                    MMAB(d[mt][nt], ah[mt][0], ah[mt][1], ah[mt][2], ah[mt][3],
                         bh[nt*2], bh[nt*2+1]);
                    MMAB(d[mt][nt], ah[mt][0], ah[mt][1], ah[mt][2], ah[mt][3],
                         bl[nt*2], bl[nt*2+1]);
                }
            #pragma unroll
            for (int mt = 0; mt < 4; ++mt) {
                uint32_t off = (uint32_t)((arow + mt * 16) * 128 + acol) ^ (uint32_t)((arow & 7) << 4);
                LDSM4(ah[mt][0], ah[mt][1], ah[mt][2], ah[mt][3], stgb + H_AL + off);
            }
            #pragma unroll
            for (int mt = 0; mt < 4; ++mt)
                #pragma unroll
                for (int nt = 0; nt < 4; ++nt)
                    MMAB(d[mt][nt], ah[mt][0], ah[mt][1], ah[mt][2], ah[mt][3],
                         bh[nt*2], bh[nt*2+1]);
        }
    }

    // epilogue: store h fp16, accumulate f1/f2 partials
    #pragma unroll
    for (int mt = 0; mt < 4; ++mt) {
        int mloc = mt * 16 + (lane >> 2);
        int mg   = i0 + mloc;
        float r1a = 0.f, r2a = 0.f, r1b = 0.f, r2b = 0.f;
        #pragma unroll
        for (int nt = 0; nt < 4; ++nt) {
            int col = wid * 32 + nt * 8 + (lane & 3) * 2;
            float d0 = d[mt][nt][0], d1 = d[mt][nt][1];
            float d2 = d[mt][nt][2], d3 = d[mt][nt][3];
            half2 ph = __floats2half2_rn(d0, d1);
            g_hb_hi[((size_t)mg * FO + col) >> 1] = *(uint32_t*)&ph;
            half2 qh = __floats2half2_rn(d2, d3);
            g_hb_hi[((size_t)(mg + 8) * FO + col) >> 1] = *(uint32_t*)&qh;
            r1a += d0 * a_s[col] + d1 * a_s[col + 1];
            r2a += d0 * a_s[FO + col] + d1 * a_s[FO + col + 1];
            r1b += d2 * a_s[col] + d3 * a_s[col + 1];
            r2b += d2 * a_s[FO + col] + d3 * a_s[FO + col + 1];
        }
        r1a += __shfl_xor_sync(0xffffffffu, r1a, 1); r1a += __shfl_xor_sync(0xffffffffu, r1a, 2);
        r2a += __shfl_xor_sync(0xffffffffu, r2a, 1); r2a += __shfl_xor_sync(0xffffffffu, r2a, 2);
        r1b += __shfl_xor_sync(0xffffffffu, r1b, 1); r1b += __shfl_xor_sync(0xffffffffu, r1b, 2);
        r2b += __shfl_xor_sync(0xffffffffu, r2b, 1); r2b += __shfl_xor_sync(0xffffffffu, r2b, 2);
        if ((lane & 3) == 0) {
            atomicAdd(&s1_s[mloc], r1a);
            atomicAdd(&s2_s[mloc], r2a);
            atomicAdd(&s1_s[mloc + 8], r1b);
            atomicAdd(&s2_s[mloc + 8], r2b);
        }
    }
    __syncthreads();
    if (t < 64) { g_f1[i0 + t] = s1_s[t]; g_f2[i0 + t] = s2_s[t]; }
    if (t < 64) {
        float m = s2_s[t];
        #pragma unroll
        for (int off = 16; off; off >>= 1)
            m = fmaxf(m, __shfl_xor_sync(0xffffffffu, m, off));
        if ((t & 31) == 0) atomicMax(&g_m2i, fkey(m));
    }
}

// ---------------------------------------------------------------------------
// k_attn: fused attention, fp16 single-B pass, 1 sync/tile software pipeline.
//  Buffers: A x2 (16K) | B x3 (32K) | adj x2 (34816)
// ---------------------------------------------------------------------------
#define A_OFF(p)   ((uint32_t)(p) * 16384u)
#define B_OFF(p)   (32768u + (uint32_t)(p) * 32768u)
#define ADJ_OFF(p) (131072u + (uint32_t)(p) * 34816u)
#define SMEM_C     200704

__device__ __forceinline__ void issue_attn(uint32_t sb, int bufB, int bufA,
                                           const int* __restrict__ adj,
                                           int i0, int jb, int t) {
    uint32_t stgB = sb + B_OFF(bufB);
    uint32_t stgJ = sb + ADJ_OFF(bufA);
    #pragma unroll
    for (int l = 0; l < 4; ++l) {          // B_hi: 2048 chunks
        int id = t + l * 512;
        int j = id >> 5, c = id & 31;
        uint32_t dst = stgB + (j << 9) + ((c * 16) ^ ((j & 7) << 4));
        const char* sh = (const char*)g_hb_hi + ((size_t)(jb + j) * FO + c * 8) * 2;
        CPA16(dst, sh);
    }
    #pragma unroll
    for (int l = 0; l < 4; ++l) {          // adj: 2048 chunks, 272B rows
        int id = t + l * 512;
        int r = id >> 4, c = id & 15;
        uint32_t dst = stgJ + r * 272 + c * 16;
        const void* src = adj + (size_t)(i0 + r) * NN + jb + c * 4;
        CPA16(dst, src);
    }
}

__global__ void __launch_bounds__(THREADS, 1)
k_attn(const int* __restrict__ adj) {
    extern __shared__ char sm[];
    uint32_t sb = smem_u32(sm);

    int t    = threadIdx.x;
    int lane = t & 31, wid = t >> 5;
    int wm   = wid & 1, wn = wid >> 1;
    int bx   = blockIdx.x;
    int i0   = (bx >> 1) * MROWS;
    int half = bx & 1;
    int jb0  = half * KHALF;

    int   wr  = t & 127, wq = t >> 7;      // w-compute: row, j-16-group
    float f1r = g_f1[i0 + wr];
    float m2  = funkey(g_m2i);
    float bsh = fmaxf(f1r + m2, 0.f);      // per-row exponent shift

    float d[4][4][4];
    #pragma unroll
    for (int m = 0; m < 4; ++m)
        #pragma unroll
        for (int n = 0; n < 4; ++n)
            #pragma unroll
            for (int c = 0; c < 4; ++c) d[m][n][c] = 0.f;
    float dpart = 0.f;

    // ---- w-compute for tile u: adj[u&1] -> A[u&1] ----
    auto wcompute = [&](int u) {
        const char* adjp = sm + ADJ_OFF(u & 1) + wr * 272 + wq * 64;
        char*       ap   = sm + A_OFF(u & 1);
        int4 a0 = *(const int4*)(adjp);
        int4 a1 = *(const int4*)(adjp + 16);
        int4 a2 = *(const int4*)(adjp + 32);
        int4 a3 = *(const int4*)(adjp + 48);
        int jq = jb0 + u * KT + wq * 16;
        float4 f20 = *(const float4*)(g_f2 + jq);
        float4 f21 = *(const float4*)(g_f2 + jq + 4);
        float4 f22 = *(const float4*)(g_f2 + jq + 8);
        float4 f23 = *(const float4*)(g_f2 + jq + 12);
        int   av[16] = {a0.x,a0.y,a0.z,a0.w, a1.x,a1.y,a1.z,a1.w,
                        a2.x,a2.y,a2.z,a2.w, a3.x,a3.y,a3.z,a3.w};
        float fv[16] = {f20.x,f20.y,f20.z,f20.w, f21.x,f21.y,f21.z,f21.w,
                        f22.x,f22.y,f22.z,f22.w, f23.x,f23.y,f23.z,f23.w};
        float w[16];
        #pragma unroll
        for (int e = 0; e < 16; ++e) {
            float sc = f1r + fv[e];
            float lr = sc > 0.f ? sc : ALPHA * sc;
            float sv = (av[e] > 0) ? lr : MASKF;
            w[e] = __expf(sv - bsh);
        }
        uint32_t hi[8];
        #pragma unroll
        for (int p = 0; p < 8; ++p) {
            half2 hp = __floats2half2_rn(w[2*p], w[2*p+1]);
            hi[p] = *(uint32_t*)&hp;
            dpart += __low2float(hp) + __high2float(hp);
        }
        uint32_t base = (uint32_t)(wr * 128 + wq * 32);
        uint32_t xo   = (uint32_t)((wr & 7) << 4);
        *(uint4*)(ap + (base ^ xo))        = make_uint4(hi[0], hi[1], hi[2], hi[3]);
        *(uint4*)(ap + ((base + 16) ^ xo)) = make_uint4(hi[4], hi[5], hi[6], hi[7]);
    };

    // ---- prologue: stage 0 and 1 in flight; wcompute(0) ----
    issue_attn(sb, 0, 0, adj, i0, jb0, t);           CPA_COMMIT();
    issue_attn(sb, 1, 1, adj, i0, jb0 + KT, t);      CPA_COMMIT();
    CPA_WAITG(1);
    __syncthreads();
    wcompute(0);

    int bB = 0;
    for (int s = 0; s < TILES; ++s) {
        CPA_WAITG(0);
        __syncthreads();                  // A(s) + stage(s+1) visible

        int s2 = s + 2;
        int bB2 = bB + 2; if (bB2 >= 3) bB2 -= 3;
        if (s2 < TILES) {
            issue_attn(sb, bB2, s & 1, adj, i0, jb0 + s2 * KT, t);
            CPA_COMMIT();
        }
        if (s + 1 < TILES) wcompute(s + 1);

        // ---- mma(s): A[s&1], B[bB] ----
        uint32_t stgA = sb + A_OFF(s & 1);
        uint32_t stgB = sb + B_OFF(bB);
        #pragma unroll
        for (int k0 = 0; k0 < KT; k0 += 16) {
            uint32_t ah[4][4], bh[8];
            int arow = wm * 64 + (lane & 15);
            int acol = (k0 + ((lane >> 4) << 3)) * 2;
            int bj = k0 + (lane & 7) + ((lane & 8) ? 8 : 0);
            #pragma unroll
            for (int hB = 0; hB < 2; ++hB) {
                int f = wn * 32 + hB * 16 + ((lane & 16) ? 8 : 0);
                uint32_t off = ((uint32_t)bj << 9) + (((uint32_t)f * 2) ^ ((bj & 7) << 4));
                LDSM4T(bh[hB*4+0], bh[hB*4+1], bh[hB*4+2], bh[hB*4+3], stgB + off);
            }
            #pragma unroll
            for (int mt = 0; mt < 4; ++mt) {
                uint32_t off = (uint32_t)((arow + mt * 16) * 128 + acol) ^ (uint32_t)((arow & 7) << 4);
                LDSM4(ah[mt][0], ah[mt][1], ah[mt][2], ah[mt][3], stgA + off);
            }
            #pragma unroll
            for (int mt = 0; mt < 4; ++mt)
                #pragma unroll
                for (int nt = 0; nt < 4; ++nt)
                    MMAH(d[mt][nt], ah[mt][0], ah[mt][1], ah[mt][2], ah[mt][3],
                         bh[nt*2], bh[nt*2+1]);
        }
        bB = bB + 1; if (bB == 3) bB = 0;
    }

    // denominators (g_pd zeroed by k_conv)
    atomicAdd(&g_pd[(size_t)half * NN + i0 + wr], dpart);

    // numerator partials
    float* base = g_pn + (size_t)half * NN * FO;
    #pragma unroll
    for (int mt = 0; mt < 4; ++mt) {
        int m = wm * 64 + mt * 16 + (lane >> 2);
        #pragma unroll
        for (int nt = 0; nt < 4; ++nt) {
            int col = wn * 32 + nt * 8 + (lane & 3) * 2;
            float* dst = base + (size_t)(i0 + m) * FO + col;
            *(float2*)dst            = make_float2(d[mt][nt][0], d[mt][nt][1]);
            *(float2*)(dst + 8 * FO) = make_float2(d[mt][nt][2], d[mt][nt][3]);
        }
    }
}

// ---------------------------------------------------------------------------
// k_norm: combine K-split halves + normalize (per-row scale cancels)
// ---------------------------------------------------------------------------
__global__ void k_norm(float* __restrict__ out) {
    int idx = blockIdx.x * 256 + threadIdx.x;
    const float4* p0 = (const float4*)g_pn;
    const float4* p1 = (const float4*)(g_pn + (size_t)NN * FO);
    float4 a = p0[idx], b = p1[idx];
    int row = idx >> 6;
    float inv = 1.f / (g_pd[row] + g_pd[NN + row]);
    float4 o;
    o.x = (a.x + b.x) * inv;
    o.y = (a.y + b.y) * inv;
    o.z = (a.z + b.z) * inv;
    o.w = (a.w + b.w) * inv;
    ((float4*)out)[idx] = o;
}

// ---------------------------------------------------------------------------
extern "C" void kernel_launch(void* const* d_in, const int* in_sizes, int n_in,
                              void* d_out, int out_size) {
    const float* x   = (const float*)d_in[0];
    const int*   adj = (const int*)  d_in[1];
    const float* W   = (const float*)d_in[2];
    const float* a   = (const float*)d_in[3];
    float*       out = (float*)d_out;

    cudaFuncSetAttribute(k_h_mma, cudaFuncAttributeMaxDynamicSharedMemorySize, SMEM_H);
    cudaFuncSetAttribute(k_attn,  cudaFuncAttributeMaxDynamicSharedMemorySize, SMEM_C);

    k_conv <<<(XPAIRS + WPAIRS) / 256, 256>>>(x, W);
    k_h_mma<<<128, 256, SMEM_H>>>(a);
    k_attn <<<128, THREADS, SMEM_C>>>(adj);
    k_norm <<<2048, 256>>>(out);
}

// round 7
// speedup vs baseline: 6.2481x; 1.0295x over previous
#include <cuda_runtime.h>
#include <cuda_bf16.h>
#include <cuda_fp16.h>
#include <cstdint>

#define NN   8192
#define FIN  512
#define FO   256
#define ALPHA 0.2f
#define MASKF 9e-15f

#define KT     64
#define MROWS  128
#define THREADS 512
#define NPART  4

#define XPAIRS (NN*FIN/2)
#define WPAIRS (FIN*FO/2)

// Scratch (device globals — no allocation allowed)
__device__ __align__(16) uint32_t g_xb_hi[XPAIRS];
__device__ __align__(16) uint32_t g_xb_lo[XPAIRS];
__device__ __align__(16) uint32_t g_wb_hi[WPAIRS];
__device__ __align__(16) uint32_t g_wb_lo[WPAIRS];
__device__ __align__(16) uint32_t g_hb_hi[NN * FO / 2];   // fp16x2 [i][f]
__device__ __align__(16) float    g_pn   [NPART * NN * FO];
__device__ __align__(16) float    g_pd   [NPART * NN];
__device__ __align__(16) float    g_f1   [NN];
__device__ __align__(16) float    g_f2   [NN];
__device__ uint32_t g_m2i;                                 // ordered-int max f2

// ---------------------------------------------------------------------------
// helpers
// ---------------------------------------------------------------------------
__device__ __forceinline__ uint32_t smem_u32(const void* p) {
    uint32_t a;
    asm("{ .reg .u64 t; cvta.to.shared.u64 t, %1; cvt.u32.u64 %0, t; }"
        : "=r"(a) : "l"(p));
    return a;
}
__device__ __forceinline__ uint32_t bfx2(float lo, float hi) {
    uint32_t r;
    asm("cvt.rn.bf16x2.f32 %0, %1, %2;" : "=r"(r) : "f"(hi), "f"(lo));
    return r;
}
__device__ __forceinline__ float bf_lo_f(uint32_t p) { return __uint_as_float(p << 16); }
__device__ __forceinline__ float bf_hi_f(uint32_t p) { return __uint_as_float(p & 0xFFFF0000u); }

__device__ __forceinline__ uint32_t fkey(float f) {
    uint32_t b = __float_as_uint(f);
    return (b & 0x80000000u) ? ~b : (b | 0x80000000u);
}
__device__ __forceinline__ float funkey(uint32_t k) {
    uint32_t b = (k & 0x80000000u) ? (k & 0x7FFFFFFFu) : ~k;
    return __uint_as_float(b);
}

#define CPA16(dst, src) \
    asm volatile("cp.async.cg.shared.global [%0], [%1], 16;" :: "r"(dst), "l"(src) : "memory")
#define CPA_COMMIT() asm volatile("cp.async.commit_group;" ::: "memory")
#define CPA_WAITG(n) asm volatile("cp.async.wait_group %0;" :: "n"(n) : "memory")

#define LDSM4(R0,R1,R2,R3,addr) \
    asm volatile("ldmatrix.sync.aligned.m8n8.x4.shared.b16 {%0,%1,%2,%3}, [%4];" \
        : "=r"(R0), "=r"(R1), "=r"(R2), "=r"(R3) : "r"(addr))
#define LDSM4T(R0,R1,R2,R3,addr) \
    asm volatile("ldmatrix.sync.aligned.m8n8.x4.trans.shared.b16 {%0,%1,%2,%3}, [%4];" \
        : "=r"(R0), "=r"(R1), "=r"(R2), "=r"(R3) : "r"(addr))

#define MMAB(D, a0,a1,a2,a3, b0,b1) \
    asm volatile("mma.sync.aligned.m16n8k16.row.col.f32.bf16.bf16.f32 " \
        "{%0,%1,%2,%3}, {%4,%5,%6,%7}, {%8,%9}, {%0,%1,%2,%3};" \
        : "+f"((D)[0]), "+f"((D)[1]), "+f"((D)[2]), "+f"((D)[3]) \
        : "r"(a0), "r"(a1), "r"(a2), "r"(a3), "r"(b0), "r"(b1))

#define MMAH(D, a0,a1,a2,a3, b0,b1) \
    asm volatile("mma.sync.aligned.m16n8k16.row.col.f32.f16.f16.f32 " \
        "{%0,%1,%2,%3}, {%4,%5,%6,%7}, {%8,%9}, {%0,%1,%2,%3};" \
        : "+f"((D)[0]), "+f"((D)[1]), "+f"((D)[2]), "+f"((D)[3]) \
        : "r"(a0), "r"(a1), "r"(a2), "r"(a3), "r"(b0), "r"(b1))

// ---------------------------------------------------------------------------
// k_conv: fp32 -> bf16 hi/lo split of x and W; zero g_pn/g_pd; init g_m2i
// ---------------------------------------------------------------------------
__global__ void k_conv(const float* __restrict__ x, const float* __restrict__ W) {
    int idx = blockIdx.x * 256 + threadIdx.x;
    if (idx == 0) g_m2i = 0u;
    if (idx < NPART * NN) g_pd[idx] = 0.f;
    if (idx < NPART * NN * FO / 4)
        ((float4*)g_pn)[idx] = make_float4(0.f, 0.f, 0.f, 0.f);
    if (idx < XPAIRS) {
        float2 v = ((const float2*)x)[idx];
        uint32_t h = bfx2(v.x, v.y);
        g_xb_hi[idx] = h;
        g_xb_lo[idx] = bfx2(v.x - bf_lo_f(h), v.y - bf_hi_f(h));
    } else if (idx < XPAIRS + WPAIRS) {
        int j = idx - XPAIRS;
        float2 v = ((const float2*)W)[j];
        uint32_t h = bfx2(v.x, v.y);
        g_wb_hi[j] = h;
        g_wb_lo[j] = bfx2(v.x - bf_lo_f(h), v.y - bf_hi_f(h));
    }
}

// ---------------------------------------------------------------------------
// k_h_mma: h = x @ W on mma.sync bf16 3-term; 512 threads (16 warps, 2Mx8N,
//          warp tile 32x32). Epilogue: g_hb fp16, f1/f2, max-f2.
// ---------------------------------------------------------------------------
#define HSTG     81920
#define H_AH     0
#define H_AL     8192
#define H_BH     16384
#define H_BL     49152
#define SMEM_H   (2 * HSTG)

__device__ __forceinline__ void issue_h(uint32_t stg, int i0, int k0, int t) {
    {   // A: 512 chunks per array
        int row = t >> 3, c = t & 7;
        uint32_t dst = stg + H_AH + row * 128 + ((c * 16) ^ ((row & 7) << 4));
        const char* sh = (const char*)g_xb_hi + ((size_t)(i0 + row) * FIN + k0 + c * 8) * 2;
        const char* sl = (const char*)g_xb_lo + ((size_t)(i0 + row) * FIN + k0 + c * 8) * 2;
        CPA16(dst, sh);
        CPA16(dst + (H_AL - H_AH), sl);
    }
    #pragma unroll
    for (int l = 0; l < 4; ++l) {   // B: 2048 chunks per array
        int id = t + l * 512;
        int kk = id >> 5, c = id & 31;
        uint32_t dst = stg + H_BH + (kk << 9) + ((c * 16) ^ ((kk & 7) << 4));
        const char* sh = (const char*)g_wb_hi + ((size_t)(k0 + kk) * FO + c * 8) * 2;
        const char* sl = (const char*)g_wb_lo + ((size_t)(k0 + kk) * FO + c * 8) * 2;
        CPA16(dst, sh);
        CPA16(dst + (H_BL - H_BH), sl);
    }
}

__global__ void __launch_bounds__(512, 1)
k_h_mma(const float* __restrict__ a) {
    extern __shared__ char sm[];
    __shared__ float a_s[2 * FO];
    __shared__ float s1_s[64], s2_s[64];
    uint32_t sb = smem_u32(sm);
    int t = threadIdx.x, lane = t & 31, wid = t >> 5;
    int wm = wid & 1, wn = wid >> 1;
    int i0 = blockIdx.x * 64;

    a_s[t] = a[t];
    if (t < 64) { s1_s[t] = 0.f; s2_s[t] = 0.f; }

    float d[2][4][4];
    #pragma unroll
    for (int m = 0; m < 2; ++m)
        #pragma unroll
        for (int n = 0; n < 4; ++n)
            #pragma unroll
            for (int c = 0; c < 4; ++c) d[m][n][c] = 0.f;

    issue_h(sb, i0, 0, t);
    CPA_COMMIT();

    for (int kc = 0; kc < 8; ++kc) {
        int s = kc & 1;
        uint32_t stgb = sb + s * HSTG;
        CPA_WAITG(0);
        __syncthreads();
        if (kc + 1 < 8) { issue_h(sb + (s ^ 1) * HSTG, i0, (kc + 1) * 64, t); CPA_COMMIT(); }

        #pragma unroll
        for (int k0 = 0; k0 < 64; k0 += 16) {
            uint32_t ah[2][4], bh[8], bl[8];
            int arow = wm * 32 + (lane & 15);
            int acol = (k0 + ((lane >> 4) << 3)) * 2;
            int bj = k0 + (lane & 7) + ((lane & 8) ? 8 : 0);
            #pragma unroll
            for (int hB = 0; hB < 2; ++hB) {
                int f = wn * 32 + hB * 16 + ((lane & 16) ? 8 : 0);
                uint32_t off = ((uint32_t)bj << 9) + (((uint32_t)f * 2) ^ ((bj & 7) << 4));
                LDSM4T(bh[hB*4+0], bh[hB*4+1], bh[hB*4+2], bh[hB*4+3], stgb + H_BH + off);
                LDSM4T(bl[hB*4+0], bl[hB*4+1], bl[hB*4+2], bl[hB*4+3], stgb + H_BL + off);
            }
            #pragma unroll
            for (int mt = 0; mt < 2; ++mt) {
                uint32_t off = (uint32_t)((arow + mt * 16) * 128 + acol) ^ (uint32_t)((arow & 7) << 4);
                LDSM4(ah[mt][0], ah[mt][1], ah[mt][2], ah[mt][3], stgb + H_AH + off);
            }
            #pragma unroll
            for (int mt = 0; mt < 2; ++mt)
                #pragma unroll
                for (int nt = 0; nt < 4; ++nt) {
                    MMAB(d[mt][nt], ah[mt][0], ah[mt][1], ah[mt][2], ah[mt][3],
                         bh[nt*2], bh[nt*2+1]);
                    MMAB(d[mt][nt], ah[mt][0], ah[mt][1], ah[mt][2], ah[mt][3],
                         bl[nt*2], bl[nt*2+1]);
                }
            #pragma unroll
            for (int mt = 0; mt < 2; ++mt) {
                uint32_t off = (uint32_t)((arow + mt * 16) * 128 + acol) ^ (uint32_t)((arow & 7) << 4);
                LDSM4(ah[mt][0], ah[mt][1], ah[mt][2], ah[mt][3], stgb + H_AL + off);
            }
            #pragma unroll
            for (int mt = 0; mt < 2; ++mt)
                #pragma unroll
                for (int nt = 0; nt < 4; ++nt)
                    MMAB(d[mt][nt], ah[mt][0], ah[mt][1], ah[mt][2], ah[mt][3],
                         bh[nt*2], bh[nt*2+1]);
        }
    }

    // epilogue: store h fp16, accumulate f1/f2 partials
    #pragma unroll
    for (int mt = 0; mt < 2; ++mt) {
        int mloc = wm * 32 + mt * 16 + (lane >> 2);
        int mg   = i0 + mloc;
        float r1a = 0.f, r2a = 0.f, r1b = 0.f, r2b = 0.f;
        #pragma unroll
        for (int nt = 0; nt < 4; ++nt) {
            int col = wn * 32 + nt * 8 + (lane & 3) * 2;
            float d0 = d[mt][nt][0], d1 = d[mt][nt][1];
            float d2 = d[mt][nt][2], d3 = d[mt][nt][3];
            half2 ph = __floats2half2_rn(d0, d1);
            g_hb_hi[((size_t)mg * FO + col) >> 1] = *(uint32_t*)&ph;
            half2 qh = __floats2half2_rn(d2, d3);
            g_hb_hi[((size_t)(mg + 8) * FO + col) >> 1] = *(uint32_t*)&qh;
            r1a += d0 * a_s[col] + d1 * a_s[col + 1];
            r2a += d0 * a_s[FO + col] + d1 * a_s[FO + col + 1];
            r1b += d2 * a_s[col] + d3 * a_s[col + 1];
            r2b += d2 * a_s[FO + col] + d3 * a_s[FO + col + 1];
        }
        r1a += __shfl_xor_sync(0xffffffffu, r1a, 1); r1a += __shfl_xor_sync(0xffffffffu, r1a, 2);
        r2a += __shfl_xor_sync(0xffffffffu, r2a, 1); r2a += __shfl_xor_sync(0xffffffffu, r2a, 2);
        r1b += __shfl_xor_sync(0xffffffffu, r1b, 1); r1b += __shfl_xor_sync(0xffffffffu, r1b, 2);
        r2b += __shfl_xor_sync(0xffffffffu, r2b, 1); r2b += __shfl_xor_sync(0xffffffffu, r2b, 2);
        if ((lane & 3) == 0) {
            atomicAdd(&s1_s[mloc], r1a);
            atomicAdd(&s2_s[mloc], r2a);
            atomicAdd(&s1_s[mloc + 8], r1b);
            atomicAdd(&s2_s[mloc + 8], r2b);
        }
    }
    __syncthreads();
    if (t < 64) {
        g_f1[i0 + t] = s1_s[t];
        g_f2[i0 + t] = s2_s[t];
        float m = s2_s[t];
        #pragma unroll
        for (int off = 16; off; off >>= 1)
            m = fmaxf(m, __shfl_xor_sync(0xffffffffu, m, off));
        if ((t & 31) == 0) atomicMax(&g_m2i, fkey(m));
    }
}

// ---------------------------------------------------------------------------
// k_attn: 148 balanced CTAs over flattened tile space (8192 = 52x56 + 96x55).
//  rb = g>>7 (128-row block), jt = g&127. Flush to partial buffer on rb change.
//  part = bx - firstCTA(rb)  (exclusive writer per (rb, part)).
// ---------------------------------------------------------------------------
#define A_OFF(p)   ((uint32_t)(p) * 16384u)
#define B_OFF(p)   (32768u + (uint32_t)(p) * 32768u)
#define ADJ_OFF(p) (131072u + (uint32_t)(p) * 34816u)
#define SMEM_C     200704

__device__ __forceinline__ int first_cta(int rb) {
    int T = rb << 7;
    return (T < 2912) ? (T / 56) : (52 + (T - 2912) / 55);
}

__device__ __forceinline__ void issue_attn(uint32_t sb, int bufB, int bufA,
                                           const int* __restrict__ adj,
                                           int g, int t) {
    int i0 = (g >> 7) << 7;
    int jb = (g & 127) << 6;
    uint32_t stgB = sb + B_OFF(bufB);
    uint32_t stgJ = sb + ADJ_OFF(bufA);
    #pragma unroll
    for (int l = 0; l < 4; ++l) {          // B_hi: 2048 chunks
        int id = t + l * 512;
        int j = id >> 5, c = id & 31;
        uint32_t dst = stgB + (j << 9) + ((c * 16) ^ ((j & 7) << 4));
        const char* sh = (const char*)g_hb_hi + ((size_t)(jb + j) * FO + c * 8) * 2;
        CPA16(dst, sh);
    }
    #pragma unroll
    for (int l = 0; l < 4; ++l) {          // adj: 2048 chunks, 272B rows
        int id = t + l * 512;
        int r = id >> 4, c = id & 15;
        uint32_t dst = stgJ + r * 272 + c * 16;
        const void* src = adj + (size_t)(i0 + r) * NN + jb + c * 4;
        CPA16(dst, src);
    }
}

__global__ void __launch_bounds__(THREADS, 1)
k_attn(const int* __restrict__ adj) {
    extern __shared__ char sm[];
    uint32_t sb = smem_u32(sm);

    int t    = threadIdx.x;
    int lane = t & 31, wid = t >> 5;
    int wm   = wid & 1, wn = wid >> 1;
    int bx   = blockIdx.x;
    int st   = (bx < 52) ? bx * 56 : 2912 + (bx - 52) * 55;
    int cnt  = (bx < 52) ? 56 : 55;

    int   wr = t & 127, wq = t >> 7;       // w-compute: row, j-16-group
    float m2 = funkey(g_m2i);

    float d[4][4][4];
    #pragma unroll
    for (int m = 0; m < 4; ++m)
        #pragma unroll
        for (int n = 0; n < 4; ++n)
            #pragma unroll
            for (int c = 0; c < 4; ++c) d[m][n][c] = 0.f;
    float dpart = 0.f, pend[2] = {0.f, 0.f};

    // ---- w-compute for global tile g into A[bufA]; returns denom partial ----
    auto wcompute = [&](int g, int bufA) -> float {
        const char* adjp = sm + ADJ_OFF(bufA) + wr * 272 + wq * 64;
        char*       ap   = sm + A_OFF(bufA);
        float f1r = g_f1[((g >> 7) << 7) + wr];
        float bsh = fmaxf(f1r + m2, 0.f);
        int4 a0 = *(const int4*)(adjp);
        int4 a1 = *(const int4*)(adjp + 16);
        int4 a2 = *(const int4*)(adjp + 32);
        int4 a3 = *(const int4*)(adjp + 48);
        int jq = ((g & 127) << 6) + wq * 16;
        float4 f20 = *(const float4*)(g_f2 + jq);
        float4 f21 = *(const float4*)(g_f2 + jq + 4);
        float4 f22 = *(const float4*)(g_f2 + jq + 8);
        float4 f23 = *(const float4*)(g_f2 + jq + 12);
        int   av[16] = {a0.x,a0.y,a0.z,a0.w, a1.x,a1.y,a1.z,a1.w,
                        a2.x,a2.y,a2.z,a2.w, a3.x,a3.y,a3.z,a3.w};
        float fv[16] = {f20.x,f20.y,f20.z,f20.w, f21.x,f21.y,f21.z,f21.w,
                        f22.x,f22.y,f22.z,f22.w, f23.x,f23.y,f23.z,f23.w};
        float w[16];
        #pragma unroll
        for (int e = 0; e < 16; ++e) {
            float sc = f1r + fv[e];
            float lr = sc > 0.f ? sc : ALPHA * sc;
            float sv = (av[e] > 0) ? lr : MASKF;
            w[e] = __expf(sv - bsh);
        }
        float dsum = 0.f;
        uint32_t hi[8];
        #pragma unroll
        for (int p = 0; p < 8; ++p) {
            half2 hp = __floats2half2_rn(w[2*p], w[2*p+1]);
            hi[p] = *(uint32_t*)&hp;
            dsum += __low2float(hp) + __high2float(hp);
        }
        uint32_t base = (uint32_t)(wr * 128 + wq * 32);
        uint32_t xo   = (uint32_t)((wr & 7) << 4);
        *(uint4*)(ap + (base ^ xo))        = make_uint4(hi[0], hi[1], hi[2], hi[3]);
        *(uint4*)(ap + ((base + 16) ^ xo)) = make_uint4(hi[4], hi[5], hi[6], hi[7]);
        return dsum;
    };

    // ---- prologue ----
    issue_attn(sb, 0, 0, adj, st, t);      CPA_COMMIT();
    issue_attn(sb, 1, 1, adj, st + 1, t);  CPA_COMMIT();
    CPA_WAITG(1);
    __syncthreads();
    pend[0] = wcompute(st, 0);

    int bB = 0;
    for (int u = 0; u < cnt; ++u) {
        CPA_WAITG(0);
        __syncthreads();                   // A(u) + stage(u+1) visible

        int bB2 = bB + 2; if (bB2 >= 3) bB2 -= 3;
        if (u + 2 < cnt) {
            issue_attn(sb, bB2, u & 1, adj, st + u + 2, t);
            CPA_COMMIT();
        }
        if (u + 1 < cnt) pend[(u + 1) & 1] = wcompute(st + u + 1, (u + 1) & 1);

        // ---- mma(u): A[u&1], B[bB] ----
        uint32_t stgA = sb + A_OFF(u & 1);
        uint32_t stgB = sb + B_OFF(bB);
        #pragma unroll
        for (int k0 = 0; k0 < KT; k0 += 16) {
            uint32_t ah[4][4], bh[8];
            int arow = wm * 64 + (lane & 15);
            int acol = (k0 + ((lane >> 4) << 3)) * 2;
            int bj = k0 + (lane & 7) + ((lane & 8) ? 8 : 0);
            #pragma unroll
            for (int hB = 0; hB < 2; ++hB) {
                int f = wn * 32 + hB * 16 + ((lane & 16) ? 8 : 0);
                uint32_t off = ((uint32_t)bj << 9) + (((uint32_t)f * 2) ^ ((bj & 7) << 4));
                LDSM4T(bh[hB*4+0], bh[hB*4+1], bh[hB*4+2], bh[hB*4+3], stgB + off);
            }
            #pragma unroll
            for (int mt = 0; mt < 4; ++mt) {
                uint32_t off = (uint32_t)((arow + mt * 16) * 128 + acol) ^ (uint32_t)((arow & 7) << 4);
                LDSM4(ah[mt][0], ah[mt][1], ah[mt][2], ah[mt][3], stgA + off);
            }
            #pragma unroll
            for (int mt = 0; mt < 4; ++mt)
                #pragma unroll
                for (int nt = 0; nt < 4; ++nt)
                    MMAH(d[mt][nt], ah[mt][0], ah[mt][1], ah[mt][2], ah[mt][3],
                         bh[nt*2], bh[nt*2+1]);
        }
        bB = bB + 1; if (bB == 3) bB = 0;

        // ---- denom bookkeeping + flush on rb boundary / end ----
        dpart += pend[u & 1];
        int g = st + u;
        bool lastu = (u == cnt - 1);
        if (lastu || (((g + 1) >> 7) != (g >> 7))) {
            int rb   = g >> 7;
            int part = bx - first_cta(rb);
            int i0   = rb << 7;
            atomicAdd(&g_pd[(size_t)part * NN + i0 + wr], dpart);
            dpart = 0.f;
            float* basep = g_pn + (size_t)part * NN * FO;
            #pragma unroll
            for (int mt = 0; mt < 4; ++mt) {
                int m = wm * 64 + mt * 16 + (lane >> 2);
                #pragma unroll
                for (int nt = 0; nt < 4; ++nt) {
                    int col = wn * 32 + nt * 8 + (lane & 3) * 2;
                    float* dst = basep + (size_t)(i0 + m) * FO + col;
                    *(float2*)dst            = make_float2(d[mt][nt][0], d[mt][nt][1]);
                    *(float2*)(dst + 8 * FO) = make_float2(d[mt][nt][2], d[mt][nt][3]);
                    d[mt][nt][0] = 0.f; d[mt][nt][1] = 0.f;
                    d[mt][nt][2] = 0.f; d[mt][nt][3] = 0.f;
                }
            }
        }
    }
}

// ---------------------------------------------------------------------------
// k_norm: combine 4 partials + normalize (per-rb scale cancels)
// ---------------------------------------------------------------------------
__global__ void k_norm(float* __restrict__ out) {
    int idx = blockIdx.x * 256 + threadIdx.x;
    int row = idx >> 6;
    float4 acc = make_float4(0.f, 0.f, 0.f, 0.f);
    float den = 0.f;
    #pragma unroll
    for (int p = 0; p < NPART; ++p) {
        float4 v = ((const float4*)(g_pn + (size_t)p * NN * FO))[idx];
        acc.x += v.x; acc.y += v.y; acc.z += v.z; acc.w += v.w;
        den += g_pd[(size_t)p * NN + row];
    }
    float inv = 1.f / den;
    ((float4*)out)[idx] = make_float4(acc.x * inv, acc.y * inv,
                                      acc.z * inv, acc.w * inv);
}

// ---------------------------------------------------------------------------
extern "C" void kernel_launch(void* const* d_in, const int* in_sizes, int n_in,
                              void* d_out, int out_size) {
    const float* x   = (const float*)d_in[0];
    const int*   adj = (const int*)  d_in[1];
    const float* W   = (const float*)d_in[2];
    const float* a   = (const float*)d_in[3];
    float*       out = (float*)d_out;

    cudaFuncSetAttribute(k_h_mma, cudaFuncAttributeMaxDynamicSharedMemorySize, SMEM_H);
    cudaFuncSetAttribute(k_attn,  cudaFuncAttributeMaxDynamicSharedMemorySize, SMEM_C);

    k_conv <<<(XPAIRS + WPAIRS) / 256, 256>>>(x, W);
    k_h_mma<<<128, 512, SMEM_H>>>(a);
    k_attn <<<148, THREADS, SMEM_C>>>(adj);
    k_norm <<<2048, 256>>>(out);
}